// round 15
// baseline (speedup 1.0000x reference)
#include <cuda_runtime.h>
#include <cuda_fp16.h>
#include <math.h>
#include <stdint.h>

// ------------------------------------------------------------------
// Arena (words). Aliasing: d2<->h1 region, d1<->h2 region.
//  h1hi 0 (34,078,720 w), h1lo 34078720, h2hi 68157440 (17,301,504 w),
//  h2lo 85458944, h3 102760448 (f32), ze 119537664, zq 121634816 (uint)
//  total 123731968 words
// ------------------------------------------------------------------
__device__ float g_arena[123731968];
__device__ __half g_xhi[6340608];       // x padded [32][3][256][258]
__device__ __half g_xlo[6340608];
__device__ float g_wtp[32768];          // 1x1 SIMT [k][m]
__device__ __half g_w1hi[6144];         // conv1 packed frag-major
__device__ __half g_w1lo[6144];
__device__ __half g_w2hi[524288];       // conv2
__device__ __half g_w2lo[524288];
__device__ __half g_w3hi[2097152];      // conv3
__device__ __half g_w3lo[2097152];
__device__ __half g_wd1[262144];        // convT1 [par] (hi only)
__device__ __half g_wd2[524288];        // convT2 [par] (hi only)
__device__ float g_vqe2[512];
__device__ float g_vqpart[256];

// ------------------------------------------------------------------
// Helpers
// ------------------------------------------------------------------
__device__ __forceinline__ uint32_t smem_u32(const void* p) {
    uint32_t a;
    asm("{ .reg .u64 t; cvta.to.shared.u64 t, %1; cvt.u32.u64 %0, t; }"
        : "=r"(a) : "l"(p));
    return a;
}
__device__ __forceinline__ void cpasync16(uint32_t dst, const void* src) {
    asm volatile("cp.async.cg.shared.global [%0], [%1], 16;"
                 :: "r"(dst), "l"(src));
}
__device__ __forceinline__ void cpasync4z(uint32_t dst, const void* src,
                                          uint32_t sz) {
    asm volatile("cp.async.ca.shared.global [%0], [%1], 4, %2;"
                 :: "r"(dst), "l"(src), "r"(sz));
}
#define CP_COMMIT() asm volatile("cp.async.commit_group;" ::: "memory")
#define CP_WAIT1()  asm volatile("cp.async.wait_group 1;" ::: "memory")
#define CP_WAIT0()  asm volatile("cp.async.wait_group 0;" ::: "memory")

__device__ __forceinline__ void mma16(float* d, const uint32_t* a,
                                      const uint32_t* b) {
    asm volatile(
        "mma.sync.aligned.m16n8k16.row.col.f32.f16.f16.f32 "
        "{%0,%1,%2,%3},{%4,%5,%6,%7},{%8,%9},{%0,%1,%2,%3};"
        : "+f"(d[0]), "+f"(d[1]), "+f"(d[2]), "+f"(d[3])
        : "r"(a[0]), "r"(a[1]), "r"(a[2]), "r"(a[3]),
          "r"(b[0]), "r"(b[1]));
}

__device__ __forceinline__ uint32_t packhi(float v) {
    return (uint32_t)__half_as_ushort(__float2half_rn(v));
}

// fragment-major pack: half-index of element (mr, kk) within a
// 128m x 16k block (2048 halves), matching m16n8k16 A fragment.
__device__ __forceinline__ int packoffH(int mr, int kk) {
    int wmh = mr >> 6, mi = (mr >> 4) & 3, r8 = (mr >> 3) & 1, gp = mr & 7;
    int tg = (kk & 7) >> 1, khi = kk >> 3, h = kk & 1;
    int w = (((wmh * 4 + mi) * 32) + gp * 4 + tg) * 4 + (r8 + 2 * khi);
    return w * 2 + h;
}

// ------------------------------------------------------------------
// Transforms (3 pre-launches total)
// ------------------------------------------------------------------
__global__ void halo_zero(__half* __restrict__ h1hi, __half* __restrict__ h1lo,
                          __half* __restrict__ h2hi, __half* __restrict__ h2lo) {
    int idx = blockIdx.x * 256 + threadIdx.x;
    __half z = __float2half(0.f);
    if (idx < 524288) {                       // h1: rows 32*128*128, Wp=130
        size_t r = (size_t)idx * 130;
        h1hi[r] = z; h1hi[r + 129] = z;
        h1lo[r] = z; h1lo[r + 129] = z;
    } else if (idx < 1048576) {               // h2: rows 32*256*64, Wp=66
        size_t r = (size_t)(idx - 524288) * 66;
        h2hi[r] = z; h2hi[r + 65] = z;
        h2lo[r] = z; h2lo[r + 65] = z;
    }
}

__global__ void xform_misc(const float* __restrict__ ew1, __half* __restrict__ w1hi,
                           __half* __restrict__ w1lo,
                           const float* __restrict__ pw, float* __restrict__ wtp,
                           const float* __restrict__ dw1, __half* __restrict__ wd1,
                           const float* __restrict__ dw2, __half* __restrict__ wd2,
                           const float* __restrict__ emb, float* __restrict__ e2) {
    int idx = blockIdx.x * 256 + threadIdx.x;
    if (idx < 6144) {                       // conv1: Cout=128, K=48
        int m = idx / 48, k = idx - m * 48;
        float v = ew1[idx];
        __half h = __float2half_rn(v);
        int dest = (k >> 4) * 2048 + packoffH(m & 127, k & 15);
        w1hi[dest] = h;
        w1lo[dest] = __float2half_rn(v - __half2float(h));
    } else if (idx < 38912) {               // 1x1: Cout=64, CK=512
        int i = idx - 6144;
        int co = i / 512, k = i - co * 512;
        wtp[k * 64 + co] = pw[i];
    } else if (idx < 301056) {              // convT1: Cin=64, Cout=256, K=256
        int i = idx - 38912;
        int par = i >> 16, rem = i & 65535;
        int o = rem >> 8, kidx = rem & 255;
        int ci = kidx >> 2, dh = (kidx >> 1) & 1, dw = kidx & 1;
        int py = par >> 1, px = par & 1;
        int kh = 2 * dh + 1 - py, kw = 2 * dw + 1 - px;
        float v = dw1[((ci * 256 + o) * 4 + kh) * 4 + kw];
        int dest = par * 65536 + ((o >> 7) * 16 + (kidx >> 4)) * 2048 +
                   packoffH(o & 127, kidx & 15);
        wd1[dest] = __float2half_rn(v);
    } else if (idx < 825344) {              // convT2: Cin=256, Cout=128, K=1024
        int i = idx - 301056;
        int par = i >> 17, rem = i & 131071;
        int o = rem >> 10, kidx = rem & 1023;
        int ci = kidx >> 2, dh = (kidx >> 1) & 1, dw = kidx & 1;
        int py = par >> 1, px = par & 1;
        int kh = 2 * dh + 1 - py, kw = 2 * dw + 1 - px;
        float v = dw2[((ci * 128 + o) * 4 + kh) * 4 + kw];
        int dest = par * 131072 + (kidx >> 4) * 2048 + packoffH(o, kidx & 15);
        wd2[dest] = __float2half_rn(v);
    } else if (idx < 825856) {              // e2
        int c = idx - 825344;
        float s = 0.f;
        for (int d = 0; d < 64; d++) {
            float e = emb[c * 64 + d];
            s += e * e;
        }
        e2[c] = s;
    }
}

// conv2/conv3 pack + x split into padded hi/lo planes
__global__ void pack_fwd(const float* __restrict__ ew2, __half* __restrict__ w2hi,
                         __half* __restrict__ w2lo,
                         const float* __restrict__ ew3, __half* __restrict__ w3hi,
                         __half* __restrict__ w3lo,
                         const float* __restrict__ x, __half* __restrict__ xhi,
                         __half* __restrict__ xlo) {
    int idx = blockIdx.x * 256 + threadIdx.x;
    if (idx < 524288) {
        int m = idx >> 11, k = idx & 2047;
        float v = ew2[idx];
        __half h = __float2half_rn(v);
        int dest = ((m >> 7) * 128 + (k >> 4)) * 2048 + packoffH(m & 127, k & 15);
        w2hi[dest] = h;
        w2lo[dest] = __float2half_rn(v - __half2float(h));
    } else if (idx < 2621440) {
        int i = idx - 524288;
        int m = i >> 12, k = i & 4095;
        float v = ew3[i];
        __half h = __float2half_rn(v);
        int dest = ((m >> 7) * 256 + (k >> 4)) * 2048 + packoffH(m & 127, k & 15);
        w3hi[dest] = h;
        w3lo[dest] = __float2half_rn(v - __half2float(h));
    } else if (idx < 2621440 + 6340608) {   // x padded split [.][256][258]
        int i = idx - 2621440;
        int wp = i % 258;
        int rest = i / 258;
        __half hv = __float2half(0.f), lv = hv;
        if (wp >= 1 && wp <= 256) {
            float v = x[(size_t)rest * 256 + wp - 1];
            hv = __float2half_rn(v);
            lv = __float2half_rn(v - __half2float(hv));
        }
        xhi[i] = hv;
        xlo[i] = lv;
    }
}

// ------------------------------------------------------------------
// fp16 warp-MMA implicit GEMM, async 3-stage pipeline.
// MODE 0 (encoder): B from hi/lo half planes (W-halo, Wp=W+2); k-pair
//   = one 4B gather = one fragment word; NO PRMT, only row predicate.
//   smem B: [p=128][LDBW=10 words] per plane. SPLITS=3 always.
// MODE 2 (decoder): unchanged half2(hi,*) word gather + PRMT. SPLITS=1.
// EPI: 1=relu f32 flat; 2=relu+split halves to padded planes;
//      4=relu+packhi word scatter.
// ------------------------------------------------------------------
struct MP {
    const __half* xh;       // MODE 0 hi plane
    const __half* xl;       // MODE 0 lo plane
    const uint32_t* x;      // MODE 2 half2 words
    const uint32_t* whi;
    const uint32_t* wlo;
    const float* bias;
    void* out;
    void* out2;
    int Cin, Hin, Win, Mtot, Hout, Wout, K, sHWo, sW;
};

template <int MODE, int SPLITS, int EPI>
__global__ __launch_bounds__(256, 2) void mma_igemm(MP g) {
    extern __shared__ __align__(16) uint32_t smw[];
    constexpr int LDB = 132;    // MODE 2 words per k-row
    constexpr int LDBW = 10;    // MODE 0 words per p-row (8 + pad)
    constexpr int ABLK = (SPLITS == 3) ? 2048 : 1024;
    constexpr int BHI = ABLK;
    constexpr int BLO = ABLK + 128 * LDBW;
    constexpr int STAGE =
        (MODE == 0) ? (ABLK + 2 * 128 * LDBW) : (ABLK + 16 * LDB);

    const int t = threadIdx.x;
    const int lane = t & 31;
    const int wid = t >> 5;
    const int p0 = blockIdx.x * 128;
    const int m0 = blockIdx.y * 128;
    const int par = (MODE == 2) ? blockIdx.z : 0;
    const int py = par >> 1, px = par & 1;
    const uint32_t sbase = smem_u32(smw);
    const uint32_t* __restrict__ whiP =
        g.whi + (size_t)par * ((size_t)g.Mtot * g.K / 2) +
        ((size_t)(m0 >> 7) * (g.K >> 4)) * 1024;
    const uint32_t* __restrict__ wloP =
        (SPLITS == 3)
            ? g.wlo + ((size_t)(m0 >> 7) * (g.K >> 4)) * 1024
            : whiP;

    // B loader role
    const int lm = t & 127;
    const int kq = (t >> 7) * 8;

    // im2col decode for p = p0 + lm
    const int p = p0 + lm;
    const int n = p >> g.sHWo;
    const int rem = p & ((1 << g.sHWo) - 1);
    const int ho = rem >> g.sW, wo = rem & ((1 << g.sW) - 1);
    const int Wp = g.Win + 2;
    const int HWp = g.Hin * Wp;
    const __half* __restrict__ xnh =
        (MODE == 0) ? g.xh + (size_t)n * g.Cin * HWp : (const __half*)0;
    const __half* __restrict__ xnl =
        (MODE == 0) ? g.xl + (size_t)n * g.Cin * HWp : (const __half*)0;
    const uint32_t* __restrict__ xn =
        (MODE == 2) ? g.x + (size_t)n * g.Cin * g.Hin * g.Win
                    : (const uint32_t*)0;
    const int HW = g.Hin * g.Win;

    int rowoff[4], iwv[4];
    bool okh[4], okw[4];
    if (MODE == 0) {
#pragma unroll
        for (int kh = 0; kh < 4; kh++) {
            int ih = 2 * ho - 1 + kh;
            okh[kh] = (unsigned)ih < (unsigned)g.Hin;
            rowoff[kh] = okh[kh] ? ih * Wp : 0;
        }
    } else {
#pragma unroll
        for (int dh = 0; dh < 2; dh++) {
            int ih = ho + py - dh;
            okh[dh] = (unsigned)ih < (unsigned)g.Hin;
            rowoff[dh] = ih * g.Win;
        }
#pragma unroll
        for (int dw = 0; dw < 2; dw++) {
            int iw = wo + px - dw;
            okw[dw] = (unsigned)iw < (unsigned)g.Win;
            iwv[dw] = iw;
        }
    }

    const int wmh = wid >> 2;
    const int wn = (wid & 3) * 32;
    const int gp = lane >> 2;
    const int tg = lane & 3;

    float acc[4][4][4];
#pragma unroll
    for (int mi = 0; mi < 4; mi++)
#pragma unroll
        for (int ni = 0; ni < 4; ni++)
#pragma unroll
            for (int r = 0; r < 4; r++) acc[mi][ni][r] = 0.f;

    auto issueAB = [&](int c, int s) {
        // A (packed fp16, 16B)
        uint32_t da = sbase + (uint32_t)(s * STAGE + t * 4) * 4;
        cpasync16(da, whiP + (size_t)c * 1024 + t * 4);
        if (SPLITS == 3) {
            uint32_t d2 = sbase + (uint32_t)(s * STAGE + 1024 + t * 4) * 4;
            cpasync16(d2, wloP + (size_t)c * 1024 + t * 4);
        }
        if (MODE == 0) {
            // B: 4 k-pair gathers per plane, fragment-direct
            const __half* bh = xnh + (size_t)c * HWp;
            const __half* bl = xnl + (size_t)c * HWp;
            uint32_t dbh = sbase + (uint32_t)(s * STAGE + BHI + lm * LDBW) * 4;
            uint32_t dbl = sbase + (uint32_t)(s * STAGE + BLO + lm * LDBW) * 4;
#pragma unroll
            for (int j2 = 0; j2 < 4; j2++) {
                int tap0 = kq + 2 * j2;
                int kh = tap0 >> 2, kw0 = tap0 & 3;
                uint32_t sz = okh[kh] ? 4u : 0u;
                int srcoff = rowoff[kh] + 2 * wo + kw0;
                uint32_t dw4 = (uint32_t)(tap0 >> 1) * 4;
                cpasync4z(dbh + dw4, bh + srcoff, sz);
                cpasync4z(dbl + dw4, bl + srcoff, sz);
            }
        } else {
            uint32_t db = sbase + (uint32_t)(s * STAGE + ABLK) * 4;
#pragma unroll
            for (int j = 0; j < 8; j++) {
                int tap = kq + j;
                int cl = tap >> 2, dd = tap & 3;
                int dh = dd >> 1, dw = dd & 1;
                bool ok = okh[dh] && okw[dw];
                const uint32_t* src = xn + (size_t)(c * 4 + cl) * HW +
                                      (ok ? rowoff[dh] + iwv[dw] : 0);
                cpasync4z(db + (uint32_t)(tap * LDB + lm) * 4, src,
                          ok ? 4u : 0u);
            }
        }
        CP_COMMIT();
    };

    auto compute = [&](int s) {
        const uint32_t* S = smw + s * STAGE;
        const uint4* A4 = (const uint4*)S;
        uint32_t bhi[4][2], blo[4][2];
        if (MODE == 0) {
#pragma unroll
            for (int ni = 0; ni < 4; ni++) {
                int pc = wn + ni * 8 + gp;
                bhi[ni][0] = S[BHI + pc * LDBW + tg];
                bhi[ni][1] = S[BHI + pc * LDBW + tg + 4];
                blo[ni][0] = S[BLO + pc * LDBW + tg];
                blo[ni][1] = S[BLO + pc * LDBW + tg + 4];
            }
        } else {
#pragma unroll
            for (int ni = 0; ni < 4; ni++) {
                int pc = wn + ni * 8 + gp;
                uint32_t w0 = S[ABLK + (2 * tg) * LDB + pc];
                uint32_t w1 = S[ABLK + (2 * tg + 1) * LDB + pc];
                uint32_t w2 = S[ABLK + (2 * tg + 8) * LDB + pc];
                uint32_t w3 = S[ABLK + (2 * tg + 9) * LDB + pc];
                bhi[ni][0] = __byte_perm(w0, w1, 0x5410);
                bhi[ni][1] = __byte_perm(w2, w3, 0x5410);
            }
        }
#pragma unroll
        for (int mi = 0; mi < 4; mi++) {
            const int fidx = (wmh * 4 + mi) * 32 + lane;
            uint4 ah4 = A4[fidx];
            uint32_t ah[4] = {ah4.x, ah4.y, ah4.z, ah4.w};
#pragma unroll
            for (int ni = 0; ni < 4; ni++) mma16(acc[mi][ni], ah, bhi[ni]);
            if (SPLITS == 3) {
                uint4 al4 = A4[256 + fidx];
                uint32_t al[4] = {al4.x, al4.y, al4.z, al4.w};
#pragma unroll
                for (int ni = 0; ni < 4; ni++) mma16(acc[mi][ni], al, bhi[ni]);
#pragma unroll
                for (int ni = 0; ni < 4; ni++) mma16(acc[mi][ni], ah, blo[ni]);
            }
        }
    };

    const int nc = g.K >> 4;
    issueAB(0, 0);
    if (nc > 1) issueAB(1, 1);
    for (int c = 0; c < nc; c++) {
        if (c < nc - 1) CP_WAIT1(); else CP_WAIT0();
        __syncthreads();
        if (c + 2 < nc) issueAB(c + 2, (c + 2) % 3);
        compute(c % 3);
    }

    // epilogue
    const int HWo = 1 << g.sHWo;
    const int nn = p0 >> g.sHWo;
    const int rem0 = p0 & (HWo - 1);
    const int WpO = g.Wout + 2;
#pragma unroll
    for (int mi = 0; mi < 4; mi++) {
        const int mA = m0 + wmh * 64 + mi * 16 + gp;
        const int mB = mA + 8;
        const float bA = g.bias[mA];
        const float bB = g.bias[mB];
#pragma unroll
        for (int ni = 0; ni < 4; ni++) {
            const int col = wn + ni * 8 + 2 * tg;
            float v0 = fmaxf(acc[mi][ni][0] + bA, 0.f);
            float v1 = fmaxf(acc[mi][ni][1] + bA, 0.f);
            float v2 = fmaxf(acc[mi][ni][2] + bB, 0.f);
            float v3 = fmaxf(acc[mi][ni][3] + bB, 0.f);
            if (MODE == 0) {
                if (EPI == 2) {
                    int rr = rem0 + col;
                    int hh = rr >> g.sW, ww = rr & ((1 << g.sW) - 1);
                    __half* OH = (__half*)g.out;
                    __half* OL = (__half*)g.out2;
                    size_t iA =
                        ((size_t)(nn * g.Mtot + mA) * g.Hout + hh) * WpO + ww + 1;
                    size_t iB =
                        ((size_t)(nn * g.Mtot + mB) * g.Hout + hh) * WpO + ww + 1;
                    __half h0 = __float2half_rn(v0);
                    __half h1 = __float2half_rn(v1);
                    __half h2v = __float2half_rn(v2);
                    __half h3v = __float2half_rn(v3);
                    OH[iA] = h0; OH[iA + 1] = h1;
                    OH[iB] = h2v; OH[iB + 1] = h3v;
                    OL[iA] = __float2half_rn(v0 - __half2float(h0));
                    OL[iA + 1] = __float2half_rn(v1 - __half2float(h1));
                    OL[iB] = __float2half_rn(v2 - __half2float(h2v));
                    OL[iB + 1] = __float2half_rn(v3 - __half2float(h3v));
                } else {
                    float* O = (float*)g.out;
                    size_t oA = ((size_t)nn * g.Mtot + mA) * HWo + rem0 + col;
                    size_t oB = ((size_t)nn * g.Mtot + mB) * HWo + rem0 + col;
                    float2 qa = {v0, v1}, qb = {v2, v3};
                    *(float2*)&O[oA] = qa;
                    *(float2*)&O[oB] = qb;
                }
            } else {
                int rr = rem0 + col;
                int hh = rr >> g.sW, ww = rr & ((1 << g.sW) - 1);
                size_t r0 = ((size_t)nn * g.Mtot + mA) * g.Hout + 2 * hh + py;
                size_t r1 = ((size_t)nn * g.Mtot + mB) * g.Hout + 2 * hh + py;
                if (EPI == 4) {
                    uint32_t* O = (uint32_t*)g.out;
                    O[r0 * g.Wout + 2 * ww + px] = packhi(v0);
                    O[r0 * g.Wout + 2 * (ww + 1) + px] = packhi(v1);
                    O[r1 * g.Wout + 2 * ww + px] = packhi(v2);
                    O[r1 * g.Wout + 2 * (ww + 1) + px] = packhi(v3);
                } else {
                    float* O = (float*)g.out;
                    O[r0 * g.Wout + 2 * ww + px] = v0;
                    O[r0 * g.Wout + 2 * (ww + 1) + px] = v1;
                    O[r1 * g.Wout + 2 * ww + px] = v2;
                    O[r1 * g.Wout + 2 * (ww + 1) + px] = v3;
                }
            }
        }
    }
}

// ------------------------------------------------------------------
// SIMT implicit GEMM (1x1 conv only, fp32)
// ------------------------------------------------------------------
struct GP {
    const float* x;
    const float* wt;
    const float* bias;
    float* out;
    int Cin, Hin, Win, M, K, sHWo, sW;
};

template <int ACT>
__global__ __launch_bounds__(256) void igemm1x1(GP g) {
    __shared__ __align__(16) float As[16][64];
    __shared__ __align__(16) float Bs[16][64];
    const int t = threadIdx.x;
    const int p0 = blockIdx.x * 64;
    const int m0 = blockIdx.y * 64;
    const int lc = t & 63, lr = t >> 6;
    const int tx = t & 15, ty = t >> 4;

    const int pB = p0 + lc;
    const int nB = pB >> g.sHWo;
    const int remB = pB & ((1 << g.sHWo) - 1);
    const float* __restrict__ xn = g.x + (size_t)nB * g.Cin * g.Hin * g.Win;

    float acc[4][4];
#pragma unroll
    for (int i = 0; i < 4; i++)
#pragma unroll
        for (int j = 0; j < 4; j++) acc[i][j] = 0.f;

    for (int k0 = 0; k0 < g.K; k0 += 16) {
#pragma unroll
        for (int j = 0; j < 4; j++) {
            int r = lr + 4 * j;
            As[r][lc] = g.wt[(size_t)(k0 + r) * g.M + m0 + lc];
            Bs[r][lc] = xn[(size_t)(k0 + r) * g.Win + remB];
        }
        __syncthreads();
#pragma unroll
        for (int kk = 0; kk < 16; kk++) {
            float4 a4 = *(const float4*)&As[kk][ty * 4];
            float4 b4 = *(const float4*)&Bs[kk][tx * 4];
            float av[4] = {a4.x, a4.y, a4.z, a4.w};
            float bv[4] = {b4.x, b4.y, b4.z, b4.w};
#pragma unroll
            for (int i = 0; i < 4; i++)
#pragma unroll
                for (int j = 0; j < 4; j++) acc[i][j] += av[i] * bv[j];
        }
        __syncthreads();
    }

    const int HWo = 1 << g.sHWo;
#pragma unroll
    for (int j = 0; j < 4; j++) {
        int p = p0 + tx * 4 + j;
        int nn = p >> g.sHWo;
        int rm = p & (HWo - 1);
#pragma unroll
        for (int i = 0; i < 4; i++) {
            int m = m0 + ty * 4 + i;
            float v = acc[i][j] + g.bias[m];
            if (ACT == 1) v = fmaxf(v, 0.f);
            g.out[((size_t)nn * g.M + m) * HWo + rm] = v;
        }
    }
}

// ------------------------------------------------------------------
// VQ (dot-product form) + loss; zq written as half2(hi,0) words
// ------------------------------------------------------------------
__global__ __launch_bounds__(128) void vq_kernel(
    const float* __restrict__ ze, const float* __restrict__ emb,
    const float* __restrict__ e2, uint32_t* __restrict__ zq,
    float* __restrict__ partial) {
    __shared__ float es[8192];
    __shared__ float e2s[128];
    __shared__ float red[128];
    const int t = threadIdx.x;
    const int pos = blockIdx.x * 128 + t;
    const int n = pos >> 10;
    const int hw = pos & 1023;

    float xv[64];
    const float* zp = ze + (size_t)n * 65536 + hw;
    float x2 = 0.f;
#pragma unroll
    for (int d = 0; d < 64; d++) {
        xv[d] = zp[(size_t)d * 1024];
        x2 += xv[d] * xv[d];
    }

    float best = 3.0e38f;
    int bidx = 0;
    for (int c0 = 0; c0 < 512; c0 += 128) {
        __syncthreads();
        {
            const float4* src = (const float4*)(emb + c0 * 64);
            float4* dst = (float4*)es;
            for (int i = t; i < 2048; i += 128) dst[i] = src[i];
            e2s[t] = e2[c0 + t];
        }
        __syncthreads();
        for (int c = 0; c < 128; c++) {
            float dot = 0.f;
            const float4* ep = (const float4*)(es + c * 64);
#pragma unroll
            for (int q = 0; q < 16; q++) {
                float4 e4 = ep[q];
                dot += xv[q * 4] * e4.x + xv[q * 4 + 1] * e4.y +
                       xv[q * 4 + 2] * e4.z + xv[q * 4 + 3] * e4.w;
            }
            float sc = e2s[c] - 2.f * dot;
            if (sc < best) { best = sc; bidx = c0 + c; }
        }
    }
    const float* e = emb + (size_t)bidx * 64;
    uint32_t* q = zq + (size_t)n * 65536 + hw;
#pragma unroll
    for (int d = 0; d < 64; d++) q[(size_t)d * 1024] = packhi(e[d]);

    red[t] = x2 + best;
    __syncthreads();
    for (int s = 64; s > 0; s >>= 1) {
        if (t < s) red[t] += red[t + s];
        __syncthreads();
    }
    if (t == 0) partial[blockIdx.x] = red[0];
}

__global__ void vq_loss_kernel(const float* __restrict__ partial,
                               float* __restrict__ out_loss) {
    __shared__ float red[256];
    int t = threadIdx.x;
    red[t] = partial[t];
    __syncthreads();
    for (int s = 128; s > 0; s >>= 1) {
        if (t < s) red[t] += red[t + s];
        __syncthreads();
    }
    if (t == 0) out_loss[0] = red[0] * (2.0f / 2097152.0f);
}

// ------------------------------------------------------------------
// convT3 v2: smem-tiled direct + sigmoid (d2 fp32)
// ------------------------------------------------------------------
__global__ __launch_bounds__(256) void convt3_v2(
    const float* __restrict__ in, const float* __restrict__ w,
    const float* __restrict__ b, float* __restrict__ out) {
    extern __shared__ float s[];
    float* ws = s;             // 6144
    float* dat = s + 6144;     // 3*32*128 = 12288
    const int t = threadIdx.x;
    const int yq = blockIdx.y;
    const int n = blockIdx.z;
    for (int i = t; i < 6144; i += 256) ws[i] = w[i];

    const int py = t >> 7;
    const int xq = t & 127;
    float acc0[3], acc1[3];
#pragma unroll
    for (int ch = 0; ch < 3; ch++) { acc0[ch] = b[ch]; acc1[ch] = b[ch]; }

    const float* xn = in + (size_t)n * 2097152;
    for (int c0 = 0; c0 < 128; c0 += 32) {
        __syncthreads();
        for (int i = t; i < 12288; i += 256) {
            int r = i >> 12;
            int cc = (i >> 7) & 31;
            int wv = i & 127;
            int h = yq - 1 + r;
            dat[i] = ((unsigned)h < 128u)
                         ? xn[(size_t)(c0 + cc) * 16384 + h * 128 + wv] : 0.f;
        }
        __syncthreads();
        for (int cc = 0; cc < 32; cc++) {
            const float* wsc = ws + (c0 + cc) * 48;
#pragma unroll
            for (int dh = 0; dh < 2; dh++) {
                const int r = py + 1 - dh;
                const float* dr = dat + (r << 12) + (cc << 7);
                float v0 = dr[xq];
                float vm = (xq > 0) ? dr[xq - 1] : 0.f;
                float vp = (xq < 127) ? dr[xq + 1] : 0.f;
                const int kh = 2 * dh + 1 - py;
#pragma unroll
                for (int ch = 0; ch < 3; ch++) {
                    const float* wk = wsc + ch * 16 + kh * 4;
                    acc0[ch] += v0 * wk[1] + vm * wk[3];
                    acc1[ch] += vp * wk[0] + v0 * wk[2];
                }
            }
        }
    }
    const int y = 2 * yq + py;
#pragma unroll
    for (int ch = 0; ch < 3; ch++) {
        float2 q;
        q.x = 1.f / (1.f + expf(-acc0[ch]));
        q.y = 1.f / (1.f + expf(-acc1[ch]));
        *(float2*)&out[(((size_t)n * 3 + ch) << 16) + y * 256 + 2 * xq] = q;
    }
}

// ------------------------------------------------------------------
// Launch
// ------------------------------------------------------------------
extern "C" void kernel_launch(void* const* d_in, const int* in_sizes, int n_in,
                              void* d_out, int out_size) {
    (void)in_sizes; (void)n_in; (void)out_size;
    const float* x   = (const float*)d_in[0];
    const float* ew1 = (const float*)d_in[1];
    const float* eb1 = (const float*)d_in[2];
    const float* ew2 = (const float*)d_in[3];
    const float* eb2 = (const float*)d_in[4];
    const float* ew3 = (const float*)d_in[5];
    const float* eb3 = (const float*)d_in[6];
    const float* pw  = (const float*)d_in[7];
    const float* pb  = (const float*)d_in[8];
    const float* emb = (const float*)d_in[9];
    const float* dw1 = (const float*)d_in[10];
    const float* db1 = (const float*)d_in[11];
    const float* dw2 = (const float*)d_in[12];
    const float* db2 = (const float*)d_in[13];
    const float* dw3 = (const float*)d_in[14];
    const float* db3 = (const float*)d_in[15];
    float* out = (float*)d_out;

    float *arena, *wtp, *part, *e2;
    __half *xhi, *xlo;
    __half *w1hi, *w1lo, *w2hi, *w2lo, *w3hi, *w3lo, *wd1, *wd2;
    cudaGetSymbolAddress((void**)&arena, g_arena);
    cudaGetSymbolAddress((void**)&xhi, g_xhi);
    cudaGetSymbolAddress((void**)&xlo, g_xlo);
    cudaGetSymbolAddress((void**)&wtp, g_wtp);
    cudaGetSymbolAddress((void**)&w1hi, g_w1hi);
    cudaGetSymbolAddress((void**)&w1lo, g_w1lo);
    cudaGetSymbolAddress((void**)&w2hi, g_w2hi);
    cudaGetSymbolAddress((void**)&w2lo, g_w2lo);
    cudaGetSymbolAddress((void**)&w3hi, g_w3hi);
    cudaGetSymbolAddress((void**)&w3lo, g_w3lo);
    cudaGetSymbolAddress((void**)&wd1, g_wd1);
    cudaGetSymbolAddress((void**)&wd2, g_wd2);
    cudaGetSymbolAddress((void**)&e2, g_vqe2);
    cudaGetSymbolAddress((void**)&part, g_vqpart);

    __half* h1hi = (__half*)arena;                      // 34,078,720 w region
    __half* h1lo = (__half*)(arena + 34078720);
    __half* h2hi = (__half*)(arena + 68157440);         // 17,301,504 w each
    __half* h2lo = (__half*)(arena + 85458944);
    float* h3 = arena + 102760448;
    float* ze = arena + 119537664;
    uint32_t* zq = (uint32_t*)(arena + 121634816);
    uint32_t* d1b = (uint32_t*)(arena + 68157440);      // alias h2 region
    float* d2b = arena;                                 // alias h1 region

    // smem: enc stage 4608 w -> 3 st = 55296 B; dec 3136 w -> 37632 B
    const int SME = 3 * 4608 * 4;
    const int SMD = 3 * 3136 * 4;
    const int SMT3 = (6144 + 12288) * 4;
    cudaFuncSetAttribute(mma_igemm<0, 3, 2>,
                         cudaFuncAttributeMaxDynamicSharedMemorySize, SME);
    cudaFuncSetAttribute(mma_igemm<0, 3, 1>,
                         cudaFuncAttributeMaxDynamicSharedMemorySize, SME);
    cudaFuncSetAttribute(mma_igemm<2, 1, 4>,
                         cudaFuncAttributeMaxDynamicSharedMemorySize, SMD);
    cudaFuncSetAttribute(mma_igemm<2, 1, 1>,
                         cudaFuncAttributeMaxDynamicSharedMemorySize, SMD);
    cudaFuncSetAttribute(convt3_v2,
                         cudaFuncAttributeMaxDynamicSharedMemorySize, SMT3);

    // 3 pre-launches
    halo_zero<<<4096, 256>>>(h1hi, h1lo, h2hi, h2lo);
    xform_misc<<<(825856 + 255) / 256, 256>>>(ew1, w1hi, w1lo, pw, wtp,
                                              dw1, wd1, dw2, wd2, emb, e2);
    pack_fwd<<<(8962048 + 255) / 256, 256>>>(ew2, w2hi, w2lo, ew3, w3hi,
                                             w3lo, x, xhi, xlo);

    MP m;
    m.x = (const uint32_t*)0;
    // conv1: x planes -> h1 planes
    m.xh = xhi; m.xl = xlo;
    m.whi = (const uint32_t*)w1hi; m.wlo = (const uint32_t*)w1lo;
    m.bias = eb1; m.out = h1hi; m.out2 = h1lo;
    m.Cin = 3; m.Hin = 256; m.Win = 256; m.Mtot = 128;
    m.Hout = 128; m.Wout = 128; m.K = 48; m.sHWo = 14; m.sW = 7;
    mma_igemm<0, 3, 2><<<dim3(4096, 1), 256, SME>>>(m);

    // conv2: h1 planes -> h2 planes
    m.xh = h1hi; m.xl = h1lo;
    m.whi = (const uint32_t*)w2hi; m.wlo = (const uint32_t*)w2lo;
    m.bias = eb2; m.out = h2hi; m.out2 = h2lo;
    m.Cin = 128; m.Hin = 128; m.Win = 128; m.Mtot = 256;
    m.Hout = 64; m.Wout = 64; m.K = 2048; m.sHWo = 12; m.sW = 6;
    mma_igemm<0, 3, 2><<<dim3(1024, 2), 256, SME>>>(m);

    // conv3: h2 planes -> h3 fp32 flat
    m.xh = h2hi; m.xl = h2lo;
    m.whi = (const uint32_t*)w3hi; m.wlo = (const uint32_t*)w3lo;
    m.bias = eb3; m.out = h3; m.out2 = h3;
    m.Cin = 256; m.Hin = 64; m.Win = 64; m.Mtot = 512;
    m.Hout = 32; m.Wout = 32; m.K = 4096; m.sHWo = 10; m.sW = 5;
    mma_igemm<0, 3, 1><<<dim3(256, 4), 256, SME>>>(m);

    // pre-VQ 1x1 (SIMT fp32): h3 -> ze
    GP g;
    g.x = h3; g.wt = wtp; g.bias = pb; g.out = ze;
    g.Cin = 512; g.Hin = 1; g.Win = 1024; g.M = 64;
    g.K = 512; g.sHWo = 10; g.sW = 0;
    igemm1x1<0><<<dim3(32768 / 64, 1), 256>>>(g);

    // VQ (zq as half2 words)
    vq_kernel<<<256, 128>>>(ze, emb, e2, zq, part);
    vq_loss_kernel<<<1, 256>>>(part, out + 6291456);

    // convT1 (fp16 1x): zq -> d1 (half2 words), 4 pars via grid z
    m.xh = (const __half*)0; m.xl = (const __half*)0;
    m.x = zq;
    m.whi = (const uint32_t*)wd1; m.wlo = (const uint32_t*)wd1;
    m.bias = db1; m.out = d1b; m.out2 = d1b;
    m.Cin = 64; m.Hin = 32; m.Win = 32; m.Mtot = 256;
    m.Hout = 64; m.Wout = 64; m.K = 256; m.sHWo = 10; m.sW = 5;
    mma_igemm<2, 1, 4><<<dim3(256, 2, 4), 256, SMD>>>(m);

    // convT2 (fp16 1x): d1 -> d2 fp32, 4 pars via grid z
    m.x = d1b;
    m.whi = (const uint32_t*)wd2; m.wlo = (const uint32_t*)wd2;
    m.bias = db2; m.out = d2b; m.out2 = d2b;
    m.Cin = 256; m.Hin = 64; m.Win = 64; m.Mtot = 128;
    m.Hout = 128; m.Wout = 128; m.K = 1024; m.sHWo = 12; m.sW = 6;
    mma_igemm<2, 1, 1><<<dim3(1024, 1, 4), 256, SMD>>>(m);

    // convT3 v2 (smem-tiled) + sigmoid
    convt3_v2<<<dim3(1, 128, 32), 256, SMT3>>>(d2b, dw3, db3, out);
}

// round 16
// speedup vs baseline: 1.0066x; 1.0066x over previous
#include <cuda_runtime.h>
#include <cuda_fp16.h>
#include <math.h>
#include <stdint.h>

// ------------------------------------------------------------------
// Scratch. Arena aliasing: d1<->h2 (dead after conv3), d2<->h1.
// words: h1 0 (uint), h2 67108864 (uint), h3 100663296 (f32),
//        ze 117440512 (f32), zq 119537664 (uint); total 121634816
// ------------------------------------------------------------------
__device__ float g_arena[121634816];
__device__ uint32_t g_xim[25165824];    // conv1 im2col [c][tap][p] half2
__device__ float g_wtp[32768];          // 1x1 SIMT [k][m]
__device__ __half g_w1hi[6144];         // conv1 packed frag-major
__device__ __half g_w1lo[6144];
__device__ __half g_w2hi[524288];       // conv2
__device__ __half g_w2lo[524288];
__device__ __half g_w3hi[2097152];      // conv3
__device__ __half g_w3lo[2097152];
__device__ __half g_wd1[262144];        // convT1 [par] (hi only)
__device__ __half g_wd2[524288];        // convT2 [par] (hi only)
__device__ float g_vqe2[512];
__device__ float g_vqpart[256];

// ------------------------------------------------------------------
// Helpers
// ------------------------------------------------------------------
__device__ __forceinline__ uint32_t smem_u32(const void* p) {
    uint32_t a;
    asm("{ .reg .u64 t; cvta.to.shared.u64 t, %1; cvt.u32.u64 %0, t; }"
        : "=r"(a) : "l"(p));
    return a;
}
__device__ __forceinline__ void cpasync16(uint32_t dst, const void* src) {
    asm volatile("cp.async.cg.shared.global [%0], [%1], 16;"
                 :: "r"(dst), "l"(src));
}
__device__ __forceinline__ void cpasync4z(uint32_t dst, const void* src,
                                          uint32_t sz) {
    asm volatile("cp.async.ca.shared.global [%0], [%1], 4, %2;"
                 :: "r"(dst), "l"(src), "r"(sz));
}
#define CP_COMMIT() asm volatile("cp.async.commit_group;" ::: "memory")
#define CP_WAIT1()  asm volatile("cp.async.wait_group 1;" ::: "memory")
#define CP_WAIT0()  asm volatile("cp.async.wait_group 0;" ::: "memory")

// m16n8k16 fp16 mma, f32 accum
__device__ __forceinline__ void mma16(float* d, const uint32_t* a,
                                      const uint32_t* b) {
    asm volatile(
        "mma.sync.aligned.m16n8k16.row.col.f32.f16.f16.f32 "
        "{%0,%1,%2,%3},{%4,%5,%6,%7},{%8,%9},{%0,%1,%2,%3};"
        : "+f"(d[0]), "+f"(d[1]), "+f"(d[2]), "+f"(d[3])
        : "r"(a[0]), "r"(a[1]), "r"(a[2]), "r"(a[3]),
          "r"(b[0]), "r"(b[1]));
}

// half2(hi,lo) split-pack of a float
__device__ __forceinline__ uint32_t packsplit(float v) {
    __half h = __float2half_rn(v);
    __half l = __float2half_rn(v - __half2float(h));
    return (uint32_t)__half_as_ushort(h) |
           ((uint32_t)__half_as_ushort(l) << 16);
}
__device__ __forceinline__ uint32_t packhi(float v) {
    return (uint32_t)__half_as_ushort(__float2half_rn(v));
}

// fragment-major pack: half-index of element (mr, kk) within a
// 128m x 16k block (2048 halves), matching m16n8k16 A fragment.
__device__ __forceinline__ int packoffH(int mr, int kk) {
    int wmh = mr >> 6, mi = (mr >> 4) & 3, r8 = (mr >> 3) & 1, gp = mr & 7;
    int tg = (kk & 7) >> 1, khi = kk >> 3, h = kk & 1;
    int w = (((wmh * 4 + mi) * 32) + gp * 4 + tg) * 4 + (r8 + 2 * khi);
    return w * 2 + h;
}

// ------------------------------------------------------------------
// Weight transforms (2 launches total)
// ------------------------------------------------------------------
__global__ void xform_misc(const float* __restrict__ ew1, __half* __restrict__ w1hi,
                           __half* __restrict__ w1lo,
                           const float* __restrict__ pw, float* __restrict__ wtp,
                           const float* __restrict__ dw1, __half* __restrict__ wd1,
                           const float* __restrict__ dw2, __half* __restrict__ wd2,
                           const float* __restrict__ emb, float* __restrict__ e2) {
    int idx = blockIdx.x * 256 + threadIdx.x;
    if (idx < 6144) {                       // conv1: Cout=128, K=48
        int m = idx / 48, k = idx - m * 48;
        float v = ew1[idx];
        __half h = __float2half_rn(v);
        int dest = (k >> 4) * 2048 + packoffH(m & 127, k & 15);
        w1hi[dest] = h;
        w1lo[dest] = __float2half_rn(v - __half2float(h));
    } else if (idx < 38912) {               // 1x1: Cout=64, CK=512
        int i = idx - 6144;
        int co = i / 512, k = i - co * 512;
        wtp[k * 64 + co] = pw[i];
    } else if (idx < 301056) {              // convT1: Cin=64, Cout=256, K=256
        int i = idx - 38912;
        int par = i >> 16, rem = i & 65535;
        int o = rem >> 8, kidx = rem & 255;
        int ci = kidx >> 2, dh = (kidx >> 1) & 1, dw = kidx & 1;
        int py = par >> 1, px = par & 1;
        int kh = 2 * dh + 1 - py, kw = 2 * dw + 1 - px;
        float v = dw1[((ci * 256 + o) * 4 + kh) * 4 + kw];
        int dest = par * 65536 + ((o >> 7) * 16 + (kidx >> 4)) * 2048 +
                   packoffH(o & 127, kidx & 15);
        wd1[dest] = __float2half_rn(v);
    } else if (idx < 825344) {              // convT2: Cin=256, Cout=128, K=1024
        int i = idx - 301056;
        int par = i >> 17, rem = i & 131071;
        int o = rem >> 10, kidx = rem & 1023;
        int ci = kidx >> 2, dh = (kidx >> 1) & 1, dw = kidx & 1;
        int py = par >> 1, px = par & 1;
        int kh = 2 * dh + 1 - py, kw = 2 * dw + 1 - px;
        float v = dw2[((ci * 128 + o) * 4 + kh) * 4 + kw];
        int dest = par * 131072 + (kidx >> 4) * 2048 + packoffH(o, kidx & 15);
        wd2[dest] = __float2half_rn(v);
    } else if (idx < 825856) {              // e2
        int c = idx - 825344;
        float s = 0.f;
        for (int d = 0; d < 64; d++) {
            float e = emb[c * 64 + d];
            s += e * e;
        }
        e2[c] = s;
    }
}

// conv2/conv3 pack + conv1 im2col [c][tap][p] half2 words
__global__ void pack_fwd(const float* __restrict__ ew2, __half* __restrict__ w2hi,
                         __half* __restrict__ w2lo,
                         const float* __restrict__ ew3, __half* __restrict__ w3hi,
                         __half* __restrict__ w3lo,
                         const float* __restrict__ x, uint32_t* __restrict__ xim) {
    int idx = blockIdx.x * 256 + threadIdx.x;
    if (idx < 524288) {
        int m = idx >> 11, k = idx & 2047;
        float v = ew2[idx];
        __half h = __float2half_rn(v);
        int dest = ((m >> 7) * 128 + (k >> 4)) * 2048 + packoffH(m & 127, k & 15);
        w2hi[dest] = h;
        w2lo[dest] = __float2half_rn(v - __half2float(h));
    } else if (idx < 2621440) {
        int i = idx - 524288;
        int m = i >> 12, k = i & 4095;
        float v = ew3[i];
        __half h = __float2half_rn(v);
        int dest = ((m >> 7) * 256 + (k >> 4)) * 2048 + packoffH(m & 127, k & 15);
        w3hi[dest] = h;
        w3lo[dest] = __float2half_rn(v - __half2float(h));
    } else if (idx < 2621440 + 25165824) {  // conv1 im2col
        int i = idx - 2621440;
        int c = i >> 23;                    // / (16*524288)
        int r = i & 8388607;
        int tap = r >> 19;                  // / 524288
        int p = r & 524287;
        int n = p >> 14;
        int rem = p & 16383;
        int ho = rem >> 7, wo = rem & 127;
        int kh = tap >> 2, kw = tap & 3;
        int ih = 2 * ho - 1 + kh;
        int iw = 2 * wo - 1 + kw;
        uint32_t wv = 0;
        if ((unsigned)ih < 256u && (unsigned)iw < 256u)
            wv = packsplit(x[((size_t)(n * 3 + c) * 256 + ih) * 256 + iw]);
        xim[i] = wv;
    }
}

// ------------------------------------------------------------------
// fp16 warp-MMA implicit GEMM, async 3-stage pipeline.
//   C[m][p] = sum_k W[m][k]*X[p][k]
// BM=128, BN=128, BK=16 (one m16n8k16 set per chunk); 8 warps.
// A: fragment-major packed fp16 (hi[,lo]) -> cp.async 16B.
// B smem layout [tap][LDB=132 words]:
//   MODE 0: half2(hi,lo) gather via cp.async 4B (zero-fill OOB)
//   MODE 1: dense pre-im2col [c][tap][p] -> coalesced 16B cp.async
//   MODE 2: convT parity gather (par = blockIdx.z)
// Consumer repacks k-pairs with PRMT. SPLITS: 3 products or 1.
// EPI: 1=relu f32 out; 2=relu+half2-split out; 4=relu+half2(hi) out.
// ------------------------------------------------------------------
struct MP {
    const uint32_t* x;      // half2 words (MODE 1: xim base)
    const uint32_t* whi;    // b32 view of packed A hi
    const uint32_t* wlo;
    const float* bias;
    void* out;
    int Cin, Hin, Win, Mtot, Hout, Wout, K, sHWo, sW;
};

template <int MODE, int SPLITS, int EPI>
__global__ __launch_bounds__(256, 2) void mma_igemm(MP g) {
    extern __shared__ __align__(16) uint32_t smw[];
    constexpr int LDB = 132;
    constexpr int ABLK = (SPLITS == 3) ? 2048 : 1024;  // b32 words
    constexpr int STAGE = ABLK + 16 * LDB;             // 4160 / 3136

    const int t = threadIdx.x;
    const int lane = t & 31;
    const int wid = t >> 5;
    const int p0 = blockIdx.x * 128;
    const int m0 = blockIdx.y * 128;
    const int par = (MODE == 2) ? blockIdx.z : 0;
    const int py = par >> 1, px = par & 1;
    const uint32_t sbase = smem_u32(smw);
    const uint32_t* __restrict__ whiP =
        g.whi + (size_t)par * ((size_t)g.Mtot * g.K / 2) +
        ((size_t)(m0 >> 7) * (g.K >> 4)) * 1024;
    const uint32_t* __restrict__ wloP =
        (SPLITS == 3)
            ? g.wlo + ((size_t)(m0 >> 7) * (g.K >> 4)) * 1024
            : whiP;

    // B loader role (MODE 0/2)
    const int lm = t & 127;
    const int kq = (t >> 7) * 8;

    // im2col decode for p = p0 + lm
    const int p = p0 + lm;
    const int n = p >> g.sHWo;
    const int rem = p & ((1 << g.sHWo) - 1);
    const int ho = rem >> g.sW, wo = rem & ((1 << g.sW) - 1);
    const uint32_t* __restrict__ xn =
        (MODE == 1) ? g.x : g.x + (size_t)n * g.Cin * g.Hin * g.Win;
    const int HW = g.Hin * g.Win;

    int rowoff[4], iwv[4];
    bool okh[4], okw[4];
    if (MODE == 0) {
#pragma unroll
        for (int kh = 0; kh < 4; kh++) {
            int ih = 2 * ho - 1 + kh;
            okh[kh] = (unsigned)ih < (unsigned)g.Hin;
            rowoff[kh] = ih * g.Win;
        }
#pragma unroll
        for (int kw = 0; kw < 4; kw++) {
            int iw = 2 * wo - 1 + kw;
            okw[kw] = (unsigned)iw < (unsigned)g.Win;
            iwv[kw] = iw;
        }
    } else if (MODE == 2) {
#pragma unroll
        for (int dh = 0; dh < 2; dh++) {
            int ih = ho + py - dh;
            okh[dh] = (unsigned)ih < (unsigned)g.Hin;
            rowoff[dh] = ih * g.Win;
        }
#pragma unroll
        for (int dw = 0; dw < 2; dw++) {
            int iw = wo + px - dw;
            okw[dw] = (unsigned)iw < (unsigned)g.Win;
            iwv[dw] = iw;
        }
    }

    const int wmh = wid >> 2;
    const int wn = (wid & 3) * 32;
    const int gp = lane >> 2;
    const int tg = lane & 3;

    float acc[4][4][4];
#pragma unroll
    for (int mi = 0; mi < 4; mi++)
#pragma unroll
        for (int ni = 0; ni < 4; ni++)
#pragma unroll
            for (int r = 0; r < 4; r++) acc[mi][ni][r] = 0.f;

    auto issueAB = [&](int c, int s) {
        // A (packed fp16, 16B)
        uint32_t da = sbase + (uint32_t)(s * STAGE + t * 4) * 4;
        cpasync16(da, whiP + (size_t)c * 1024 + t * 4);
        if (SPLITS == 3) {
            uint32_t d2 = sbase + (uint32_t)(s * STAGE + 1024 + t * 4) * 4;
            cpasync16(d2, wloP + (size_t)c * 1024 + t * 4);
        }
        uint32_t db = sbase + (uint32_t)(s * STAGE + ABLK) * 4;
        if (MODE == 0) {
            const uint32_t* bp = xn + (size_t)c * HW;
#pragma unroll
            for (int j = 0; j < 8; j++) {
                int tap = kq + j;
                int kh = tap >> 2, kw = tap & 3;
                bool ok = okh[kh] && okw[kw];
                const uint32_t* src = bp + (ok ? rowoff[kh] + iwv[kw] : 0);
                cpasync4z(db + (uint32_t)(tap * LDB + lm) * 4, src,
                          ok ? 4u : 0u);
            }
        } else if (MODE == 1) {
            // dense: xim[c][tap][p], coalesced
            const int tap = t >> 4;
            const int p4 = (t & 15) * 8;
            const uint32_t* src =
                xn + ((size_t)c << 23) + ((size_t)tap << 19) + p0 + p4;
            uint32_t dd = db + (uint32_t)(tap * LDB + p4) * 4;
            cpasync16(dd, src);
            cpasync16(dd + 16, src + 4);
        } else {
#pragma unroll
            for (int j = 0; j < 8; j++) {
                int tap = kq + j;
                int cl = tap >> 2, dd = tap & 3;
                int dh = dd >> 1, dw = dd & 1;
                bool ok = okh[dh] && okw[dw];
                const uint32_t* src = xn + (size_t)(c * 4 + cl) * HW +
                                      (ok ? rowoff[dh] + iwv[dw] : 0);
                cpasync4z(db + (uint32_t)(tap * LDB + lm) * 4, src,
                          ok ? 4u : 0u);
            }
        }
        CP_COMMIT();
    };

    auto compute = [&](int s) {
        const uint32_t* S = smw + s * STAGE;
        const uint4* A4 = (const uint4*)S;
        uint32_t bhi[4][2], blo[4][2];
#pragma unroll
        for (int ni = 0; ni < 4; ni++) {
            int pc = wn + ni * 8 + gp;
            uint32_t w0 = S[ABLK + (2 * tg) * LDB + pc];
            uint32_t w1 = S[ABLK + (2 * tg + 1) * LDB + pc];
            uint32_t w2 = S[ABLK + (2 * tg + 8) * LDB + pc];
            uint32_t w3 = S[ABLK + (2 * tg + 9) * LDB + pc];
            bhi[ni][0] = __byte_perm(w0, w1, 0x5410);
            bhi[ni][1] = __byte_perm(w2, w3, 0x5410);
            if (SPLITS == 3) {
                blo[ni][0] = __byte_perm(w0, w1, 0x7632);
                blo[ni][1] = __byte_perm(w2, w3, 0x7632);
            }
        }
#pragma unroll
        for (int mi = 0; mi < 4; mi++) {
            const int fidx = (wmh * 4 + mi) * 32 + lane;
            uint4 ah4 = A4[fidx];
            uint32_t ah[4] = {ah4.x, ah4.y, ah4.z, ah4.w};
#pragma unroll
            for (int ni = 0; ni < 4; ni++) mma16(acc[mi][ni], ah, bhi[ni]);
            if (SPLITS == 3) {
                uint4 al4 = A4[256 + fidx];
                uint32_t al[4] = {al4.x, al4.y, al4.z, al4.w};
#pragma unroll
                for (int ni = 0; ni < 4; ni++) mma16(acc[mi][ni], al, bhi[ni]);
#pragma unroll
                for (int ni = 0; ni < 4; ni++) mma16(acc[mi][ni], ah, blo[ni]);
            }
        }
    };

    const int nc = g.K >> 4;
    issueAB(0, 0);
    if (nc > 1) issueAB(1, 1);
    for (int c = 0; c < nc; c++) {
        if (c < nc - 1) CP_WAIT1(); else CP_WAIT0();
        __syncthreads();
        if (c + 2 < nc) issueAB(c + 2, (c + 2) % 3);
        compute(c % 3);
    }

    // epilogue
    const int HWo = 1 << g.sHWo;
    const int nn = p0 >> g.sHWo;
    const int rem0 = p0 & (HWo - 1);
#pragma unroll
    for (int mi = 0; mi < 4; mi++) {
        const int mA = m0 + wmh * 64 + mi * 16 + gp;
        const int mB = mA + 8;
        const float bA = g.bias[mA];
        const float bB = g.bias[mB];
#pragma unroll
        for (int ni = 0; ni < 4; ni++) {
            const int col = wn + ni * 8 + 2 * tg;
            float v0 = fmaxf(acc[mi][ni][0] + bA, 0.f);
            float v1 = fmaxf(acc[mi][ni][1] + bA, 0.f);
            float v2 = fmaxf(acc[mi][ni][2] + bB, 0.f);
            float v3 = fmaxf(acc[mi][ni][3] + bB, 0.f);
            if (MODE != 2) {
                size_t oA = ((size_t)nn * g.Mtot + mA) * HWo + rem0 + col;
                size_t oB = ((size_t)nn * g.Mtot + mB) * HWo + rem0 + col;
                if (EPI == 2) {
                    uint32_t* O = (uint32_t*)g.out;
                    uint2 qa = {packsplit(v0), packsplit(v1)};
                    uint2 qb = {packsplit(v2), packsplit(v3)};
                    *(uint2*)&O[oA] = qa;
                    *(uint2*)&O[oB] = qb;
                } else {
                    float* O = (float*)g.out;
                    float2 qa = {v0, v1}, qb = {v2, v3};
                    *(float2*)&O[oA] = qa;
                    *(float2*)&O[oB] = qb;
                }
            } else {
                int rr = rem0 + col;
                int hh = rr >> g.sW, ww = rr & ((1 << g.sW) - 1);
                size_t r0 = ((size_t)nn * g.Mtot + mA) * g.Hout + 2 * hh + py;
                size_t r1 = ((size_t)nn * g.Mtot + mB) * g.Hout + 2 * hh + py;
                if (EPI == 4) {
                    uint32_t* O = (uint32_t*)g.out;
                    O[r0 * g.Wout + 2 * ww + px] = packhi(v0);
                    O[r0 * g.Wout + 2 * (ww + 1) + px] = packhi(v1);
                    O[r1 * g.Wout + 2 * ww + px] = packhi(v2);
                    O[r1 * g.Wout + 2 * (ww + 1) + px] = packhi(v3);
                } else {
                    float* O = (float*)g.out;
                    O[r0 * g.Wout + 2 * ww + px] = v0;
                    O[r0 * g.Wout + 2 * (ww + 1) + px] = v1;
                    O[r1 * g.Wout + 2 * ww + px] = v2;
                    O[r1 * g.Wout + 2 * (ww + 1) + px] = v3;
                }
            }
        }
    }
}

// ------------------------------------------------------------------
// SIMT implicit GEMM (1x1 conv only, fp32)
// ------------------------------------------------------------------
struct GP {
    const float* x;
    const float* wt;
    const float* bias;
    float* out;
    int Cin, Hin, Win, M, K, sHWo, sW;
};

template <int ACT>
__global__ __launch_bounds__(256) void igemm1x1(GP g) {
    __shared__ __align__(16) float As[16][64];
    __shared__ __align__(16) float Bs[16][64];
    const int t = threadIdx.x;
    const int p0 = blockIdx.x * 64;
    const int m0 = blockIdx.y * 64;
    const int lc = t & 63, lr = t >> 6;
    const int tx = t & 15, ty = t >> 4;

    const int pB = p0 + lc;
    const int nB = pB >> g.sHWo;
    const int remB = pB & ((1 << g.sHWo) - 1);
    const float* __restrict__ xn = g.x + (size_t)nB * g.Cin * g.Hin * g.Win;

    float acc[4][4];
#pragma unroll
    for (int i = 0; i < 4; i++)
#pragma unroll
        for (int j = 0; j < 4; j++) acc[i][j] = 0.f;

    for (int k0 = 0; k0 < g.K; k0 += 16) {
#pragma unroll
        for (int j = 0; j < 4; j++) {
            int r = lr + 4 * j;
            As[r][lc] = g.wt[(size_t)(k0 + r) * g.M + m0 + lc];
            Bs[r][lc] = xn[(size_t)(k0 + r) * g.Win + remB];
        }
        __syncthreads();
#pragma unroll
        for (int kk = 0; kk < 16; kk++) {
            float4 a4 = *(const float4*)&As[kk][ty * 4];
            float4 b4 = *(const float4*)&Bs[kk][tx * 4];
            float av[4] = {a4.x, a4.y, a4.z, a4.w};
            float bv[4] = {b4.x, b4.y, b4.z, b4.w};
#pragma unroll
            for (int i = 0; i < 4; i++)
#pragma unroll
                for (int j = 0; j < 4; j++) acc[i][j] += av[i] * bv[j];
        }
        __syncthreads();
    }

    const int HWo = 1 << g.sHWo;
#pragma unroll
    for (int j = 0; j < 4; j++) {
        int p = p0 + tx * 4 + j;
        int nn = p >> g.sHWo;
        int rm = p & (HWo - 1);
#pragma unroll
        for (int i = 0; i < 4; i++) {
            int m = m0 + ty * 4 + i;
            float v = acc[i][j] + g.bias[m];
            if (ACT == 1) v = fmaxf(v, 0.f);
            g.out[((size_t)nn * g.M + m) * HWo + rm] = v;
        }
    }
}

// ------------------------------------------------------------------
// VQ (dot-product form) + loss; zq written as half2(hi,0) words
// ------------------------------------------------------------------
__global__ __launch_bounds__(128) void vq_kernel(
    const float* __restrict__ ze, const float* __restrict__ emb,
    const float* __restrict__ e2, uint32_t* __restrict__ zq,
    float* __restrict__ partial) {
    __shared__ float es[8192];
    __shared__ float e2s[128];
    __shared__ float red[128];
    const int t = threadIdx.x;
    const int pos = blockIdx.x * 128 + t;
    const int n = pos >> 10;
    const int hw = pos & 1023;

    float xv[64];
    const float* zp = ze + (size_t)n * 65536 + hw;
    float x2 = 0.f;
#pragma unroll
    for (int d = 0; d < 64; d++) {
        xv[d] = zp[(size_t)d * 1024];
        x2 += xv[d] * xv[d];
    }

    float best = 3.0e38f;
    int bidx = 0;
    for (int c0 = 0; c0 < 512; c0 += 128) {
        __syncthreads();
        {
            const float4* src = (const float4*)(emb + c0 * 64);
            float4* dst = (float4*)es;
            for (int i = t; i < 2048; i += 128) dst[i] = src[i];
            e2s[t] = e2[c0 + t];
        }
        __syncthreads();
        for (int c = 0; c < 128; c++) {
            float dot = 0.f;
            const float4* ep = (const float4*)(es + c * 64);
#pragma unroll
            for (int q = 0; q < 16; q++) {
                float4 e4 = ep[q];
                dot += xv[q * 4] * e4.x + xv[q * 4 + 1] * e4.y +
                       xv[q * 4 + 2] * e4.z + xv[q * 4 + 3] * e4.w;
            }
            float sc = e2s[c] - 2.f * dot;
            if (sc < best) { best = sc; bidx = c0 + c; }
        }
    }
    const float* e = emb + (size_t)bidx * 64;
    uint32_t* q = zq + (size_t)n * 65536 + hw;
#pragma unroll
    for (int d = 0; d < 64; d++) q[(size_t)d * 1024] = packhi(e[d]);

    red[t] = x2 + best;
    __syncthreads();
    for (int s = 64; s > 0; s >>= 1) {
        if (t < s) red[t] += red[t + s];
        __syncthreads();
    }
    if (t == 0) partial[blockIdx.x] = red[0];
}

__global__ void vq_loss_kernel(const float* __restrict__ partial,
                               float* __restrict__ out_loss) {
    __shared__ float red[256];
    int t = threadIdx.x;
    red[t] = partial[t];
    __syncthreads();
    for (int s = 128; s > 0; s >>= 1) {
        if (t < s) red[t] += red[t + s];
        __syncthreads();
    }
    if (t == 0) out_loss[0] = red[0] * (2.0f / 2097152.0f);
}

// ------------------------------------------------------------------
// convT3 v2: smem-tiled direct + sigmoid (d2 fp32)
// ------------------------------------------------------------------
__global__ __launch_bounds__(256) void convt3_v2(
    const float* __restrict__ in, const float* __restrict__ w,
    const float* __restrict__ b, float* __restrict__ out) {
    extern __shared__ float s[];
    float* ws = s;             // 6144
    float* dat = s + 6144;     // 3*32*128 = 12288
    const int t = threadIdx.x;
    const int yq = blockIdx.y;
    const int n = blockIdx.z;
    for (int i = t; i < 6144; i += 256) ws[i] = w[i];

    const int py = t >> 7;
    const int xq = t & 127;
    float acc0[3], acc1[3];
#pragma unroll
    for (int ch = 0; ch < 3; ch++) { acc0[ch] = b[ch]; acc1[ch] = b[ch]; }

    const float* xn = in + (size_t)n * 2097152;
    for (int c0 = 0; c0 < 128; c0 += 32) {
        __syncthreads();
        for (int i = t; i < 12288; i += 256) {
            int r = i >> 12;
            int cc = (i >> 7) & 31;
            int wv = i & 127;
            int h = yq - 1 + r;
            dat[i] = ((unsigned)h < 128u)
                         ? xn[(size_t)(c0 + cc) * 16384 + h * 128 + wv] : 0.f;
        }
        __syncthreads();
        for (int cc = 0; cc < 32; cc++) {
            const float* wsc = ws + (c0 + cc) * 48;
#pragma unroll
            for (int dh = 0; dh < 2; dh++) {
                const int r = py + 1 - dh;
                const float* dr = dat + (r << 12) + (cc << 7);
                float v0 = dr[xq];
                float vm = (xq > 0) ? dr[xq - 1] : 0.f;
                float vp = (xq < 127) ? dr[xq + 1] : 0.f;
                const int kh = 2 * dh + 1 - py;
#pragma unroll
                for (int ch = 0; ch < 3; ch++) {
                    const float* wk = wsc + ch * 16 + kh * 4;
                    acc0[ch] += v0 * wk[1] + vm * wk[3];
                    acc1[ch] += vp * wk[0] + v0 * wk[2];
                }
            }
        }
    }
    const int y = 2 * yq + py;
#pragma unroll
    for (int ch = 0; ch < 3; ch++) {
        float2 q;
        q.x = 1.f / (1.f + expf(-acc0[ch]));
        q.y = 1.f / (1.f + expf(-acc1[ch]));
        *(float2*)&out[(((size_t)n * 3 + ch) << 16) + y * 256 + 2 * xq] = q;
    }
}

// ------------------------------------------------------------------
// Launch
// ------------------------------------------------------------------
extern "C" void kernel_launch(void* const* d_in, const int* in_sizes, int n_in,
                              void* d_out, int out_size) {
    (void)in_sizes; (void)n_in; (void)out_size;
    const float* x   = (const float*)d_in[0];
    const float* ew1 = (const float*)d_in[1];
    const float* eb1 = (const float*)d_in[2];
    const float* ew2 = (const float*)d_in[3];
    const float* eb2 = (const float*)d_in[4];
    const float* ew3 = (const float*)d_in[5];
    const float* eb3 = (const float*)d_in[6];
    const float* pw  = (const float*)d_in[7];
    const float* pb  = (const float*)d_in[8];
    const float* emb = (const float*)d_in[9];
    const float* dw1 = (const float*)d_in[10];
    const float* db1 = (const float*)d_in[11];
    const float* dw2 = (const float*)d_in[12];
    const float* db2 = (const float*)d_in[13];
    const float* dw3 = (const float*)d_in[14];
    const float* db3 = (const float*)d_in[15];
    float* out = (float*)d_out;

    float *arena, *wtp, *part, *e2;
    uint32_t* xim;
    __half *w1hi, *w1lo, *w2hi, *w2lo, *w3hi, *w3lo, *wd1, *wd2;
    cudaGetSymbolAddress((void**)&arena, g_arena);
    cudaGetSymbolAddress((void**)&xim, g_xim);
    cudaGetSymbolAddress((void**)&wtp, g_wtp);
    cudaGetSymbolAddress((void**)&w1hi, g_w1hi);
    cudaGetSymbolAddress((void**)&w1lo, g_w1lo);
    cudaGetSymbolAddress((void**)&w2hi, g_w2hi);
    cudaGetSymbolAddress((void**)&w2lo, g_w2lo);
    cudaGetSymbolAddress((void**)&w3hi, g_w3hi);
    cudaGetSymbolAddress((void**)&w3lo, g_w3lo);
    cudaGetSymbolAddress((void**)&wd1, g_wd1);
    cudaGetSymbolAddress((void**)&wd2, g_wd2);
    cudaGetSymbolAddress((void**)&e2, g_vqe2);
    cudaGetSymbolAddress((void**)&part, g_vqpart);

    uint32_t* h1 = (uint32_t*)arena;                    // half2 words
    uint32_t* h2 = (uint32_t*)(arena + 67108864);
    float* h3 = arena + 100663296;
    float* ze = arena + 117440512;
    uint32_t* zq = (uint32_t*)(arena + 119537664);
    uint32_t* d1b = (uint32_t*)(arena + 67108864);      // alias h2
    float* d2b = arena;                                 // alias h1

    // smem: enc stage 4160 w -> 3 st = 49920 B; dec 3136 w -> 37632 B
    const int SME = 3 * 4160 * 4;
    const int SMD = 3 * 3136 * 4;
    const int SMT3 = (6144 + 12288) * 4;
    cudaFuncSetAttribute(mma_igemm<1, 3, 2>,
                         cudaFuncAttributeMaxDynamicSharedMemorySize, SME);
    cudaFuncSetAttribute(mma_igemm<0, 3, 2>,
                         cudaFuncAttributeMaxDynamicSharedMemorySize, SME);
    cudaFuncSetAttribute(mma_igemm<0, 3, 1>,
                         cudaFuncAttributeMaxDynamicSharedMemorySize, SME);
    cudaFuncSetAttribute(mma_igemm<2, 1, 4>,
                         cudaFuncAttributeMaxDynamicSharedMemorySize, SMD);
    cudaFuncSetAttribute(mma_igemm<2, 1, 1>,
                         cudaFuncAttributeMaxDynamicSharedMemorySize, SMD);
    cudaFuncSetAttribute(convt3_v2,
                         cudaFuncAttributeMaxDynamicSharedMemorySize, SMT3);

    // 2 transform launches
    xform_misc<<<(825856 + 255) / 256, 256>>>(ew1, w1hi, w1lo, pw, wtp,
                                              dw1, wd1, dw2, wd2, emb, e2);
    pack_fwd<<<(27787264 + 255) / 256, 256>>>(ew2, w2hi, w2lo, ew3, w3hi,
                                              w3lo, x, xim);

    MP m;
    // conv1 (fp16 x2-split, dense im2col B): xim -> h1 (half2)
    m.x = xim; m.whi = (const uint32_t*)w1hi; m.wlo = (const uint32_t*)w1lo;
    m.bias = eb1; m.out = h1;
    m.Cin = 3; m.Hin = 256; m.Win = 256; m.Mtot = 128;
    m.Hout = 128; m.Wout = 128; m.K = 48; m.sHWo = 14; m.sW = 7;
    mma_igemm<1, 3, 2><<<dim3(4096, 1), 256, SME>>>(m);

    // conv2: h1 -> h2 (half2)
    m.x = h1; m.whi = (const uint32_t*)w2hi; m.wlo = (const uint32_t*)w2lo;
    m.bias = eb2; m.out = h2;
    m.Cin = 128; m.Hin = 128; m.Win = 128; m.Mtot = 256;
    m.Hout = 64; m.Wout = 64; m.K = 2048; m.sHWo = 12; m.sW = 6;
    mma_igemm<0, 3, 2><<<dim3(1024, 2), 256, SME>>>(m);

    // conv3: h2 -> h3 (fp32)
    m.x = h2; m.whi = (const uint32_t*)w3hi; m.wlo = (const uint32_t*)w3lo;
    m.bias = eb3; m.out = h3;
    m.Cin = 256; m.Hin = 64; m.Win = 64; m.Mtot = 512;
    m.Hout = 32; m.Wout = 32; m.K = 4096; m.sHWo = 10; m.sW = 5;
    mma_igemm<0, 3, 1><<<dim3(256, 4), 256, SME>>>(m);

    // pre-VQ 1x1 (SIMT fp32): h3 -> ze
    GP g;
    g.x = h3; g.wt = wtp; g.bias = pb; g.out = ze;
    g.Cin = 512; g.Hin = 1; g.Win = 1024; g.M = 64;
    g.K = 512; g.sHWo = 10; g.sW = 0;
    igemm1x1<0><<<dim3(32768 / 64, 1), 256>>>(g);

    // VQ (zq as half2 words)
    vq_kernel<<<256, 128>>>(ze, emb, e2, zq, part);
    vq_loss_kernel<<<1, 256>>>(part, out + 6291456);

    // convT1 (fp16 1x): zq -> d1 (half2), 4 pars via grid z
    m.x = zq; m.whi = (const uint32_t*)wd1; m.wlo = (const uint32_t*)wd1;
    m.bias = db1; m.out = d1b;
    m.Cin = 64; m.Hin = 32; m.Win = 32; m.Mtot = 256;
    m.Hout = 64; m.Wout = 64; m.K = 256; m.sHWo = 10; m.sW = 5;
    mma_igemm<2, 1, 4><<<dim3(256, 2, 4), 256, SMD>>>(m);

    // convT2 (fp16 1x): d1 -> d2 (fp32), 4 pars via grid z
    m.x = d1b; m.whi = (const uint32_t*)wd2; m.wlo = (const uint32_t*)wd2;
    m.bias = db2; m.out = d2b;
    m.Cin = 256; m.Hin = 64; m.Win = 64; m.Mtot = 128;
    m.Hout = 128; m.Wout = 128; m.K = 1024; m.sHWo = 12; m.sW = 6;
    mma_igemm<2, 1, 1><<<dim3(1024, 1, 4), 256, SMD>>>(m);

    // convT3 v2 (smem-tiled) + sigmoid
    convt3_v2<<<dim3(1, 128, 32), 256, SMT3>>>(d2b, dw3, db3, out);
}

// round 17
// speedup vs baseline: 1.0321x; 1.0253x over previous
#include <cuda_runtime.h>
#include <cuda_fp16.h>
#include <math.h>
#include <stdint.h>

// ------------------------------------------------------------------
// Arena (f32 words). Plane layout (halves, W-halo Wp=W+2):
//  h1hi 0 (34,078,720 w) h1lo 34078720 | h2hi 68157440 (17,301,504 w)
//  h2lo 85458944 | h3 102760448 f32 | ze 119537664 | zq 121634816 uint
//  total 123731968.  Alias: d2<->h1 region, d1<->h2 region.
// ------------------------------------------------------------------
__device__ float g_arena[123731968];
__device__ uint32_t g_ximhi[12582912];  // conv1 im2col pair-words hi
__device__ uint32_t g_ximlo[12582912];  //   [c][ptap8][p]
__device__ float g_wtp[32768];          // 1x1 SIMT [k][m]
__device__ __half g_w1hi[6144];         // conv1 packed frag-major
__device__ __half g_w1lo[6144];
__device__ __half g_w2hi[524288];       // conv2
__device__ __half g_w2lo[524288];
__device__ __half g_w3hi[2097152];      // conv3
__device__ __half g_w3lo[2097152];
__device__ __half g_wd1[262144];        // convT1 [par] (hi only)
__device__ __half g_wd2[524288];        // convT2 [par] (hi only)
__device__ float g_vqe2[512];
__device__ float g_vqpart[256];

// ------------------------------------------------------------------
// Helpers
// ------------------------------------------------------------------
__device__ __forceinline__ uint32_t smem_u32(const void* p) {
    uint32_t a;
    asm("{ .reg .u64 t; cvta.to.shared.u64 t, %1; cvt.u32.u64 %0, t; }"
        : "=r"(a) : "l"(p));
    return a;
}
__device__ __forceinline__ void cpasync16(uint32_t dst, const void* src) {
    asm volatile("cp.async.cg.shared.global [%0], [%1], 16;"
                 :: "r"(dst), "l"(src));
}
__device__ __forceinline__ void cpasync4z(uint32_t dst, const void* src,
                                          uint32_t sz) {
    asm volatile("cp.async.ca.shared.global [%0], [%1], 4, %2;"
                 :: "r"(dst), "l"(src), "r"(sz));
}
#define CP_COMMIT() asm volatile("cp.async.commit_group;" ::: "memory")
#define CP_WAIT1()  asm volatile("cp.async.wait_group 1;" ::: "memory")
#define CP_WAIT0()  asm volatile("cp.async.wait_group 0;" ::: "memory")

// m16n8k16 fp16 mma, f32 accum
__device__ __forceinline__ void mma16(float* d, const uint32_t* a,
                                      const uint32_t* b) {
    asm volatile(
        "mma.sync.aligned.m16n8k16.row.col.f32.f16.f16.f32 "
        "{%0,%1,%2,%3},{%4,%5,%6,%7},{%8,%9},{%0,%1,%2,%3};"
        : "+f"(d[0]), "+f"(d[1]), "+f"(d[2]), "+f"(d[3])
        : "r"(a[0]), "r"(a[1]), "r"(a[2]), "r"(a[3]),
          "r"(b[0]), "r"(b[1]));
}

__device__ __forceinline__ uint32_t packhi(float v) {
    return (uint32_t)__half_as_ushort(__float2half_rn(v));
}

// fragment-major pack: half-index of element (mr, kk) within a
// 128m x 16k block (2048 halves), matching m16n8k16 A fragment.
__device__ __forceinline__ int packoffH(int mr, int kk) {
    int wmh = mr >> 6, mi = (mr >> 4) & 3, r8 = (mr >> 3) & 1, gp = mr & 7;
    int tg = (kk & 7) >> 1, khi = kk >> 3, h = kk & 1;
    int w = (((wmh * 4 + mi) * 32) + gp * 4 + tg) * 4 + (r8 + 2 * khi);
    return w * 2 + h;
}

// ------------------------------------------------------------------
// Pre-launches (3 total so ncu -s 5 lands on conv3)
// ------------------------------------------------------------------
__global__ void halo_zero(__half* __restrict__ h1hi, __half* __restrict__ h1lo,
                          __half* __restrict__ h2hi, __half* __restrict__ h2lo) {
    int idx = blockIdx.x * 256 + threadIdx.x;
    __half z = __float2half(0.f);
    if (idx < 524288) {                       // h1: rows 32*128*128, Wp=130
        size_t r = (size_t)idx * 130;
        h1hi[r] = z; h1hi[r + 129] = z;
        h1lo[r] = z; h1lo[r + 129] = z;
    } else if (idx < 1048576) {               // h2: rows 32*256*64, Wp=66
        size_t r = (size_t)(idx - 524288) * 66;
        h2hi[r] = z; h2hi[r + 65] = z;
        h2lo[r] = z; h2lo[r + 65] = z;
    }
}

__global__ void xform_misc(const float* __restrict__ ew1, __half* __restrict__ w1hi,
                           __half* __restrict__ w1lo,
                           const float* __restrict__ pw, float* __restrict__ wtp,
                           const float* __restrict__ dw1, __half* __restrict__ wd1,
                           const float* __restrict__ dw2, __half* __restrict__ wd2,
                           const float* __restrict__ emb, float* __restrict__ e2) {
    int idx = blockIdx.x * 256 + threadIdx.x;
    if (idx < 6144) {                       // conv1: Cout=128, K=48
        int m = idx / 48, k = idx - m * 48;
        float v = ew1[idx];
        __half h = __float2half_rn(v);
        int dest = (k >> 4) * 2048 + packoffH(m & 127, k & 15);
        w1hi[dest] = h;
        w1lo[dest] = __float2half_rn(v - __half2float(h));
    } else if (idx < 38912) {               // 1x1: Cout=64, CK=512
        int i = idx - 6144;
        int co = i / 512, k = i - co * 512;
        wtp[k * 64 + co] = pw[i];
    } else if (idx < 301056) {              // convT1: Cin=64, Cout=256, K=256
        int i = idx - 38912;
        int par = i >> 16, rem = i & 65535;
        int o = rem >> 8, kidx = rem & 255;
        int ci = kidx >> 2, dh = (kidx >> 1) & 1, dw = kidx & 1;
        int py = par >> 1, px = par & 1;
        int kh = 2 * dh + 1 - py, kw = 2 * dw + 1 - px;
        float v = dw1[((ci * 256 + o) * 4 + kh) * 4 + kw];
        int dest = par * 65536 + ((o >> 7) * 16 + (kidx >> 4)) * 2048 +
                   packoffH(o & 127, kidx & 15);
        wd1[dest] = __float2half_rn(v);
    } else if (idx < 825344) {              // convT2: Cin=256, Cout=128, K=1024
        int i = idx - 301056;
        int par = i >> 17, rem = i & 131071;
        int o = rem >> 10, kidx = rem & 1023;
        int ci = kidx >> 2, dh = (kidx >> 1) & 1, dw = kidx & 1;
        int py = par >> 1, px = par & 1;
        int kh = 2 * dh + 1 - py, kw = 2 * dw + 1 - px;
        float v = dw2[((ci * 128 + o) * 4 + kh) * 4 + kw];
        int dest = par * 131072 + (kidx >> 4) * 2048 + packoffH(o, kidx & 15);
        wd2[dest] = __float2half_rn(v);
    } else if (idx < 825856) {              // e2
        int c = idx - 825344;
        float s = 0.f;
        for (int d = 0; d < 64; d++) {
            float e = emb[c * 64 + d];
            s += e * e;
        }
        e2[c] = s;
    }
}

// conv2/conv3 pack + conv1 im2col pair-words (hi/lo)
__global__ void pack_fwd(const float* __restrict__ ew2, __half* __restrict__ w2hi,
                         __half* __restrict__ w2lo,
                         const float* __restrict__ ew3, __half* __restrict__ w3hi,
                         __half* __restrict__ w3lo,
                         const float* __restrict__ x, uint32_t* __restrict__ xhi,
                         uint32_t* __restrict__ xlo) {
    int idx = blockIdx.x * 256 + threadIdx.x;
    if (idx < 524288) {
        int m = idx >> 11, k = idx & 2047;
        float v = ew2[idx];
        __half h = __float2half_rn(v);
        int dest = ((m >> 7) * 128 + (k >> 4)) * 2048 + packoffH(m & 127, k & 15);
        w2hi[dest] = h;
        w2lo[dest] = __float2half_rn(v - __half2float(h));
    } else if (idx < 2621440) {
        int i = idx - 524288;
        int m = i >> 12, k = i & 4095;
        float v = ew3[i];
        __half h = __float2half_rn(v);
        int dest = ((m >> 7) * 256 + (k >> 4)) * 2048 + packoffH(m & 127, k & 15);
        w3hi[dest] = h;
        w3lo[dest] = __float2half_rn(v - __half2float(h));
    } else if (idx < 2621440 + 12582912) {  // conv1 im2col pair-words
        int i = idx - 2621440;
        int c = i >> 22;                    // / (8*524288)
        int r = i & 4194303;
        int ptap = r >> 19;
        int p = r & 524287;
        int n = p >> 14;
        int rem = p & 16383;
        int ho = rem >> 7, wo = rem & 127;
        int kh = ptap >> 1, kw0 = (ptap & 1) * 2;
        int ih = 2 * ho - 1 + kh;
        int iw0 = 2 * wo - 1 + kw0;
        float v0 = 0.f, v1 = 0.f;
        if ((unsigned)ih < 256u) {
            const float* row = x + ((size_t)(n * 3 + c) * 256 + ih) * 256;
            if ((unsigned)iw0 < 256u) v0 = row[iw0];
            if ((unsigned)(iw0 + 1) < 256u) v1 = row[iw0 + 1];
        }
        __half h0 = __float2half_rn(v0), h1 = __float2half_rn(v1);
        __half l0 = __float2half_rn(v0 - __half2float(h0));
        __half l1 = __float2half_rn(v1 - __half2float(h1));
        xhi[i] = (uint32_t)__half_as_ushort(h0) |
                 ((uint32_t)__half_as_ushort(h1) << 16);
        xlo[i] = (uint32_t)__half_as_ushort(l0) |
                 ((uint32_t)__half_as_ushort(l1) << 16);
    }
}

// ------------------------------------------------------------------
// fp16 warp-MMA implicit GEMM, async 3-stage pipeline.
//   C[m][p] = sum_k W[m][k]*X[p][k]
// BM=128, BN=128, BK=16; 8 warps. A: packed frag-major, cp.async 16B.
// MODE 0 (conv2/3): B from hi/lo halo planes, pair 4B gathers ->
//   smem [ptap8][LDP=136] per plane, fragment-direct (no PRMT).
// MODE 1 (conv1): B from dense pair-word buffers, coalesced 16B.
// MODE 2 (decoder): half2(hi,*) k-major gather + PRMT. SPLITS=1.
// EPI: 1=relu f32 flat; 2=relu+split to halo planes; 4=relu+packhi.
// ------------------------------------------------------------------
struct MP {
    const __half* xh;       // MODE 0 hi plane
    const __half* xl;       // MODE 0 lo plane
    const uint32_t* x;      // MODE 1 hi pairs / MODE 2 half2 words
    const uint32_t* x2;     // MODE 1 lo pairs
    const uint32_t* whi;
    const uint32_t* wlo;
    const float* bias;
    void* out;
    void* out2;
    int Cin, Hin, Win, Mtot, Hout, Wout, K, sHWo, sW;
};

template <int MODE, int SPLITS, int EPI>
__global__ __launch_bounds__(256, 2) void mma_igemm(MP g) {
    extern __shared__ __align__(16) uint32_t smw[];
    constexpr int LDB = 132;    // MODE 2 words per k-row
    constexpr int LDP = 136;    // MODE 0/1 words per pair-row
    constexpr int ABLK = (SPLITS == 3) ? 2048 : 1024;
    constexpr int BHI = ABLK;
    constexpr int BLO = ABLK + 8 * LDP;
    constexpr int STAGE =
        (MODE == 2) ? (ABLK + 16 * LDB) : (ABLK + 2 * 8 * LDP);

    const int t = threadIdx.x;
    const int lane = t & 31;
    const int wid = t >> 5;
    const int p0 = blockIdx.x * 128;
    const int m0 = blockIdx.y * 128;
    const int par = (MODE == 2) ? blockIdx.z : 0;
    const int py = par >> 1, px = par & 1;
    const uint32_t sbase = smem_u32(smw);
    const uint32_t* __restrict__ whiP =
        g.whi + (size_t)par * ((size_t)g.Mtot * g.K / 2) +
        ((size_t)(m0 >> 7) * (g.K >> 4)) * 1024;
    const uint32_t* __restrict__ wloP =
        (SPLITS == 3)
            ? g.wlo + ((size_t)(m0 >> 7) * (g.K >> 4)) * 1024
            : whiP;

    // B loader role
    const int lm = t & 127;
    const int kq = (t >> 7) * 8;

    // im2col decode for p = p0 + lm
    const int p = p0 + lm;
    const int n = p >> g.sHWo;
    const int rem = p & ((1 << g.sHWo) - 1);
    const int ho = rem >> g.sW, wo = rem & ((1 << g.sW) - 1);
    const int Wp = g.Win + 2;
    const int HWp = g.Hin * Wp;
    const __half* __restrict__ xnh =
        (MODE == 0) ? g.xh + (size_t)n * g.Cin * HWp : (const __half*)0;
    const __half* __restrict__ xnl =
        (MODE == 0) ? g.xl + (size_t)n * g.Cin * HWp : (const __half*)0;
    const uint32_t* __restrict__ xn =
        (MODE == 2) ? g.x + (size_t)n * g.Cin * g.Hin * g.Win
                    : g.x;
    const int HW = g.Hin * g.Win;

    int rowoff[4], iwv[4];
    bool okh[4], okw[4];
    if (MODE == 0) {
#pragma unroll
        for (int kh = 0; kh < 4; kh++) {
            int ih = 2 * ho - 1 + kh;
            okh[kh] = (unsigned)ih < (unsigned)g.Hin;
            rowoff[kh] = okh[kh] ? ih * Wp : 0;
        }
    } else if (MODE == 2) {
#pragma unroll
        for (int dh = 0; dh < 2; dh++) {
            int ih = ho + py - dh;
            okh[dh] = (unsigned)ih < (unsigned)g.Hin;
            rowoff[dh] = ih * g.Win;
        }
#pragma unroll
        for (int dw = 0; dw < 2; dw++) {
            int iw = wo + px - dw;
            okw[dw] = (unsigned)iw < (unsigned)g.Win;
            iwv[dw] = iw;
        }
    }

    const int wmh = wid >> 2;
    const int wn = (wid & 3) * 32;
    const int gp = lane >> 2;
    const int tg = lane & 3;

    float acc[4][4][4];
#pragma unroll
    for (int mi = 0; mi < 4; mi++)
#pragma unroll
        for (int ni = 0; ni < 4; ni++)
#pragma unroll
            for (int r = 0; r < 4; r++) acc[mi][ni][r] = 0.f;

    auto issueAB = [&](int c, int s) {
        // A (packed fp16, 16B)
        uint32_t da = sbase + (uint32_t)(s * STAGE + t * 4) * 4;
        cpasync16(da, whiP + (size_t)c * 1024 + t * 4);
        if (SPLITS == 3) {
            uint32_t d2 = sbase + (uint32_t)(s * STAGE + 1024 + t * 4) * 4;
            cpasync16(d2, wloP + (size_t)c * 1024 + t * 4);
        }
        if (MODE == 0) {
            const __half* bh = xnh + (size_t)c * HWp;
            const __half* bl = xnl + (size_t)c * HWp;
            uint32_t dbh = sbase + (uint32_t)(s * STAGE + BHI) * 4;
            uint32_t dbl = sbase + (uint32_t)(s * STAGE + BLO) * 4;
#pragma unroll
            for (int j2 = 0; j2 < 4; j2++) {
                int tap0 = kq + 2 * j2;
                int kh = tap0 >> 2, kw0 = tap0 & 3;
                uint32_t sz = okh[kh] ? 4u : 0u;
                int off = rowoff[kh] + 2 * wo + kw0;
                uint32_t dw4 = (uint32_t)((tap0 >> 1) * LDP + lm) * 4;
                cpasync4z(dbh + dw4, bh + off, sz);
                cpasync4z(dbl + dw4, bl + off, sz);
            }
        } else if (MODE == 1) {
            // dense pair-words: x/x2 [c][row8][p], coalesced 16B
            const int row = t >> 5;
            const int p4 = (t & 31) * 4;
            size_t off = (((size_t)c << 3) + row) * 524288 + p0 + p4;
            uint32_t dbh =
                sbase + (uint32_t)(s * STAGE + BHI + row * LDP + p4) * 4;
            uint32_t dbl =
                sbase + (uint32_t)(s * STAGE + BLO + row * LDP + p4) * 4;
            cpasync16(dbh, g.x + off);
            cpasync16(dbl, g.x2 + off);
        } else {
            uint32_t db = sbase + (uint32_t)(s * STAGE + ABLK) * 4;
#pragma unroll
            for (int j = 0; j < 8; j++) {
                int tap = kq + j;
                int cl = tap >> 2, dd = tap & 3;
                int dh = dd >> 1, dw = dd & 1;
                bool ok = okh[dh] && okw[dw];
                const uint32_t* src = xn + (size_t)(c * 4 + cl) * HW +
                                      (ok ? rowoff[dh] + iwv[dw] : 0);
                cpasync4z(db + (uint32_t)(tap * LDB + lm) * 4, src,
                          ok ? 4u : 0u);
            }
        }
        CP_COMMIT();
    };

    auto compute = [&](int s) {
        const uint32_t* S = smw + s * STAGE;
        const uint4* A4 = (const uint4*)S;
        uint32_t bhi[4][2], blo[4][2];
        if (MODE != 2) {
#pragma unroll
            for (int ni = 0; ni < 4; ni++) {
                int pc = wn + ni * 8 + gp;
                bhi[ni][0] = S[BHI + tg * LDP + pc];
                bhi[ni][1] = S[BHI + (tg + 4) * LDP + pc];
                blo[ni][0] = S[BLO + tg * LDP + pc];
                blo[ni][1] = S[BLO + (tg + 4) * LDP + pc];
            }
        } else {
#pragma unroll
            for (int ni = 0; ni < 4; ni++) {
                int pc = wn + ni * 8 + gp;
                uint32_t w0 = S[ABLK + (2 * tg) * LDB + pc];
                uint32_t w1 = S[ABLK + (2 * tg + 1) * LDB + pc];
                uint32_t w2 = S[ABLK + (2 * tg + 8) * LDB + pc];
                uint32_t w3 = S[ABLK + (2 * tg + 9) * LDB + pc];
                bhi[ni][0] = __byte_perm(w0, w1, 0x5410);
                bhi[ni][1] = __byte_perm(w2, w3, 0x5410);
            }
        }
#pragma unroll
        for (int mi = 0; mi < 4; mi++) {
            const int fidx = (wmh * 4 + mi) * 32 + lane;
            uint4 ah4 = A4[fidx];
            uint32_t ah[4] = {ah4.x, ah4.y, ah4.z, ah4.w};
#pragma unroll
            for (int ni = 0; ni < 4; ni++) mma16(acc[mi][ni], ah, bhi[ni]);
            if (SPLITS == 3) {
                uint4 al4 = A4[256 + fidx];
                uint32_t al[4] = {al4.x, al4.y, al4.z, al4.w};
#pragma unroll
                for (int ni = 0; ni < 4; ni++) mma16(acc[mi][ni], al, bhi[ni]);
#pragma unroll
                for (int ni = 0; ni < 4; ni++) mma16(acc[mi][ni], ah, blo[ni]);
            }
        }
    };

    const int nc = g.K >> 4;
    issueAB(0, 0);
    if (nc > 1) issueAB(1, 1);
    for (int c = 0; c < nc; c++) {
        if (c < nc - 1) CP_WAIT1(); else CP_WAIT0();
        __syncthreads();
        if (c + 2 < nc) issueAB(c + 2, (c + 2) % 3);
        compute(c % 3);
    }

    // epilogue
    const int HWo = 1 << g.sHWo;
    const int nn = p0 >> g.sHWo;
    const int rem0 = p0 & (HWo - 1);
    const int WpO = g.Wout + 2;
#pragma unroll
    for (int mi = 0; mi < 4; mi++) {
        const int mA = m0 + wmh * 64 + mi * 16 + gp;
        const int mB = mA + 8;
        const float bA = g.bias[mA];
        const float bB = g.bias[mB];
#pragma unroll
        for (int ni = 0; ni < 4; ni++) {
            const int col = wn + ni * 8 + 2 * tg;
            float v0 = fmaxf(acc[mi][ni][0] + bA, 0.f);
            float v1 = fmaxf(acc[mi][ni][1] + bA, 0.f);
            float v2 = fmaxf(acc[mi][ni][2] + bB, 0.f);
            float v3 = fmaxf(acc[mi][ni][3] + bB, 0.f);
            if (MODE != 2) {
                if (EPI == 2) {
                    int rr = rem0 + col;
                    int hh = rr >> g.sW, ww = rr & ((1 << g.sW) - 1);
                    __half* OH = (__half*)g.out;
                    __half* OL = (__half*)g.out2;
                    size_t iA =
                        ((size_t)(nn * g.Mtot + mA) * g.Hout + hh) * WpO + ww + 1;
                    size_t iB =
                        ((size_t)(nn * g.Mtot + mB) * g.Hout + hh) * WpO + ww + 1;
                    __half h0 = __float2half_rn(v0);
                    __half h1 = __float2half_rn(v1);
                    __half h2v = __float2half_rn(v2);
                    __half h3v = __float2half_rn(v3);
                    OH[iA] = h0; OH[iA + 1] = h1;
                    OH[iB] = h2v; OH[iB + 1] = h3v;
                    OL[iA] = __float2half_rn(v0 - __half2float(h0));
                    OL[iA + 1] = __float2half_rn(v1 - __half2float(h1));
                    OL[iB] = __float2half_rn(v2 - __half2float(h2v));
                    OL[iB + 1] = __float2half_rn(v3 - __half2float(h3v));
                } else {
                    float* O = (float*)g.out;
                    size_t oA = ((size_t)nn * g.Mtot + mA) * HWo + rem0 + col;
                    size_t oB = ((size_t)nn * g.Mtot + mB) * HWo + rem0 + col;
                    float2 qa = {v0, v1}, qb = {v2, v3};
                    *(float2*)&O[oA] = qa;
                    *(float2*)&O[oB] = qb;
                }
            } else {
                int rr = rem0 + col;
                int hh = rr >> g.sW, ww = rr & ((1 << g.sW) - 1);
                size_t r0 = ((size_t)nn * g.Mtot + mA) * g.Hout + 2 * hh + py;
                size_t r1 = ((size_t)nn * g.Mtot + mB) * g.Hout + 2 * hh + py;
                if (EPI == 4) {
                    uint32_t* O = (uint32_t*)g.out;
                    O[r0 * g.Wout + 2 * ww + px] = packhi(v0);
                    O[r0 * g.Wout + 2 * (ww + 1) + px] = packhi(v1);
                    O[r1 * g.Wout + 2 * ww + px] = packhi(v2);
                    O[r1 * g.Wout + 2 * (ww + 1) + px] = packhi(v3);
                } else {
                    float* O = (float*)g.out;
                    O[r0 * g.Wout + 2 * ww + px] = v0;
                    O[r0 * g.Wout + 2 * (ww + 1) + px] = v1;
                    O[r1 * g.Wout + 2 * ww + px] = v2;
                    O[r1 * g.Wout + 2 * (ww + 1) + px] = v3;
                }
            }
        }
    }
}

// ------------------------------------------------------------------
// SIMT implicit GEMM (1x1 conv only, fp32)
// ------------------------------------------------------------------
struct GP {
    const float* x;
    const float* wt;
    const float* bias;
    float* out;
    int Cin, Hin, Win, M, K, sHWo, sW;
};

template <int ACT>
__global__ __launch_bounds__(256) void igemm1x1(GP g) {
    __shared__ __align__(16) float As[16][64];
    __shared__ __align__(16) float Bs[16][64];
    const int t = threadIdx.x;
    const int p0 = blockIdx.x * 64;
    const int m0 = blockIdx.y * 64;
    const int lc = t & 63, lr = t >> 6;
    const int tx = t & 15, ty = t >> 4;

    const int pB = p0 + lc;
    const int nB = pB >> g.sHWo;
    const int remB = pB & ((1 << g.sHWo) - 1);
    const float* __restrict__ xn = g.x + (size_t)nB * g.Cin * g.Hin * g.Win;

    float acc[4][4];
#pragma unroll
    for (int i = 0; i < 4; i++)
#pragma unroll
        for (int j = 0; j < 4; j++) acc[i][j] = 0.f;

    for (int k0 = 0; k0 < g.K; k0 += 16) {
#pragma unroll
        for (int j = 0; j < 4; j++) {
            int r = lr + 4 * j;
            As[r][lc] = g.wt[(size_t)(k0 + r) * g.M + m0 + lc];
            Bs[r][lc] = xn[(size_t)(k0 + r) * g.Win + remB];
        }
        __syncthreads();
#pragma unroll
        for (int kk = 0; kk < 16; kk++) {
            float4 a4 = *(const float4*)&As[kk][ty * 4];
            float4 b4 = *(const float4*)&Bs[kk][tx * 4];
            float av[4] = {a4.x, a4.y, a4.z, a4.w};
            float bv[4] = {b4.x, b4.y, b4.z, b4.w};
#pragma unroll
            for (int i = 0; i < 4; i++)
#pragma unroll
                for (int j = 0; j < 4; j++) acc[i][j] += av[i] * bv[j];
        }
        __syncthreads();
    }

    const int HWo = 1 << g.sHWo;
#pragma unroll
    for (int j = 0; j < 4; j++) {
        int p = p0 + tx * 4 + j;
        int nn = p >> g.sHWo;
        int rm = p & (HWo - 1);
#pragma unroll
        for (int i = 0; i < 4; i++) {
            int m = m0 + ty * 4 + i;
            float v = acc[i][j] + g.bias[m];
            if (ACT == 1) v = fmaxf(v, 0.f);
            g.out[((size_t)nn * g.M + m) * HWo + rm] = v;
        }
    }
}

// ------------------------------------------------------------------
// VQ (dot-product form) + loss; zq written as half2(hi,0) words
// ------------------------------------------------------------------
__global__ __launch_bounds__(128) void vq_kernel(
    const float* __restrict__ ze, const float* __restrict__ emb,
    const float* __restrict__ e2, uint32_t* __restrict__ zq,
    float* __restrict__ partial) {
    __shared__ float es[8192];
    __shared__ float e2s[128];
    __shared__ float red[128];
    const int t = threadIdx.x;
    const int pos = blockIdx.x * 128 + t;
    const int n = pos >> 10;
    const int hw = pos & 1023;

    float xv[64];
    const float* zp = ze + (size_t)n * 65536 + hw;
    float x2 = 0.f;
#pragma unroll
    for (int d = 0; d < 64; d++) {
        xv[d] = zp[(size_t)d * 1024];
        x2 += xv[d] * xv[d];
    }

    float best = 3.0e38f;
    int bidx = 0;
    for (int c0 = 0; c0 < 512; c0 += 128) {
        __syncthreads();
        {
            const float4* src = (const float4*)(emb + c0 * 64);
            float4* dst = (float4*)es;
            for (int i = t; i < 2048; i += 128) dst[i] = src[i];
            e2s[t] = e2[c0 + t];
        }
        __syncthreads();
        for (int c = 0; c < 128; c++) {
            float dot = 0.f;
            const float4* ep = (const float4*)(es + c * 64);
#pragma unroll
            for (int q = 0; q < 16; q++) {
                float4 e4 = ep[q];
                dot += xv[q * 4] * e4.x + xv[q * 4 + 1] * e4.y +
                       xv[q * 4 + 2] * e4.z + xv[q * 4 + 3] * e4.w;
            }
            float sc = e2s[c] - 2.f * dot;
            if (sc < best) { best = sc; bidx = c0 + c; }
        }
    }
    const float* e = emb + (size_t)bidx * 64;
    uint32_t* q = zq + (size_t)n * 65536 + hw;
#pragma unroll
    for (int d = 0; d < 64; d++) q[(size_t)d * 1024] = packhi(e[d]);

    red[t] = x2 + best;
    __syncthreads();
    for (int s = 64; s > 0; s >>= 1) {
        if (t < s) red[t] += red[t + s];
        __syncthreads();
    }
    if (t == 0) partial[blockIdx.x] = red[0];
}

__global__ void vq_loss_kernel(const float* __restrict__ partial,
                               float* __restrict__ out_loss) {
    __shared__ float red[256];
    int t = threadIdx.x;
    red[t] = partial[t];
    __syncthreads();
    for (int s = 128; s > 0; s >>= 1) {
        if (t < s) red[t] += red[t + s];
        __syncthreads();
    }
    if (t == 0) out_loss[0] = red[0] * (2.0f / 2097152.0f);
}

// ------------------------------------------------------------------
// convT3 v2: smem-tiled direct + sigmoid (d2 fp32)
// ------------------------------------------------------------------
__global__ __launch_bounds__(256) void convt3_v2(
    const float* __restrict__ in, const float* __restrict__ w,
    const float* __restrict__ b, float* __restrict__ out) {
    extern __shared__ float s[];
    float* ws = s;             // 6144
    float* dat = s + 6144;     // 3*32*128 = 12288
    const int t = threadIdx.x;
    const int yq = blockIdx.y;
    const int n = blockIdx.z;
    for (int i = t; i < 6144; i += 256) ws[i] = w[i];

    const int py = t >> 7;
    const int xq = t & 127;
    float acc0[3], acc1[3];
#pragma unroll
    for (int ch = 0; ch < 3; ch++) { acc0[ch] = b[ch]; acc1[ch] = b[ch]; }

    const float* xn = in + (size_t)n * 2097152;
    for (int c0 = 0; c0 < 128; c0 += 32) {
        __syncthreads();
        for (int i = t; i < 12288; i += 256) {
            int r = i >> 12;
            int cc = (i >> 7) & 31;
            int wv = i & 127;
            int h = yq - 1 + r;
            dat[i] = ((unsigned)h < 128u)
                         ? xn[(size_t)(c0 + cc) * 16384 + h * 128 + wv] : 0.f;
        }
        __syncthreads();
        for (int cc = 0; cc < 32; cc++) {
            const float* wsc = ws + (c0 + cc) * 48;
#pragma unroll
            for (int dh = 0; dh < 2; dh++) {
                const int r = py + 1 - dh;
                const float* dr = dat + (r << 12) + (cc << 7);
                float v0 = dr[xq];
                float vm = (xq > 0) ? dr[xq - 1] : 0.f;
                float vp = (xq < 127) ? dr[xq + 1] : 0.f;
                const int kh = 2 * dh + 1 - py;
#pragma unroll
                for (int ch = 0; ch < 3; ch++) {
                    const float* wk = wsc + ch * 16 + kh * 4;
                    acc0[ch] += v0 * wk[1] + vm * wk[3];
                    acc1[ch] += vp * wk[0] + v0 * wk[2];
                }
            }
        }
    }
    const int y = 2 * yq + py;
#pragma unroll
    for (int ch = 0; ch < 3; ch++) {
        float2 q;
        q.x = 1.f / (1.f + expf(-acc0[ch]));
        q.y = 1.f / (1.f + expf(-acc1[ch]));
        *(float2*)&out[(((size_t)n * 3 + ch) << 16) + y * 256 + 2 * xq] = q;
    }
}

// ------------------------------------------------------------------
// Launch
// ------------------------------------------------------------------
extern "C" void kernel_launch(void* const* d_in, const int* in_sizes, int n_in,
                              void* d_out, int out_size) {
    (void)in_sizes; (void)n_in; (void)out_size;
    const float* x   = (const float*)d_in[0];
    const float* ew1 = (const float*)d_in[1];
    const float* eb1 = (const float*)d_in[2];
    const float* ew2 = (const float*)d_in[3];
    const float* eb2 = (const float*)d_in[4];
    const float* ew3 = (const float*)d_in[5];
    const float* eb3 = (const float*)d_in[6];
    const float* pw  = (const float*)d_in[7];
    const float* pb  = (const float*)d_in[8];
    const float* emb = (const float*)d_in[9];
    const float* dw1 = (const float*)d_in[10];
    const float* db1 = (const float*)d_in[11];
    const float* dw2 = (const float*)d_in[12];
    const float* db2 = (const float*)d_in[13];
    const float* dw3 = (const float*)d_in[14];
    const float* db3 = (const float*)d_in[15];
    float* out = (float*)d_out;

    float *arena, *wtp, *part, *e2;
    uint32_t *ximhi, *ximlo;
    __half *w1hi, *w1lo, *w2hi, *w2lo, *w3hi, *w3lo, *wd1, *wd2;
    cudaGetSymbolAddress((void**)&arena, g_arena);
    cudaGetSymbolAddress((void**)&ximhi, g_ximhi);
    cudaGetSymbolAddress((void**)&ximlo, g_ximlo);
    cudaGetSymbolAddress((void**)&wtp, g_wtp);
    cudaGetSymbolAddress((void**)&w1hi, g_w1hi);
    cudaGetSymbolAddress((void**)&w1lo, g_w1lo);
    cudaGetSymbolAddress((void**)&w2hi, g_w2hi);
    cudaGetSymbolAddress((void**)&w2lo, g_w2lo);
    cudaGetSymbolAddress((void**)&w3hi, g_w3hi);
    cudaGetSymbolAddress((void**)&w3lo, g_w3lo);
    cudaGetSymbolAddress((void**)&wd1, g_wd1);
    cudaGetSymbolAddress((void**)&wd2, g_wd2);
    cudaGetSymbolAddress((void**)&e2, g_vqe2);
    cudaGetSymbolAddress((void**)&part, g_vqpart);

    __half* h1hi = (__half*)arena;
    __half* h1lo = (__half*)(arena + 34078720);
    __half* h2hi = (__half*)(arena + 68157440);
    __half* h2lo = (__half*)(arena + 85458944);
    float* h3 = arena + 102760448;
    float* ze = arena + 119537664;
    uint32_t* zq = (uint32_t*)(arena + 121634816);
    uint32_t* d1b = (uint32_t*)(arena + 68157440);  // alias h2 region
    float* d2b = arena;                             // alias h1 region

    // smem: enc stage 4224 w -> 3 st = 50688 B; dec 3136 w -> 37632 B
    const int SME = 3 * 4224 * 4;
    const int SMD = 3 * 3136 * 4;
    const int SMT3 = (6144 + 12288) * 4;
    cudaFuncSetAttribute(mma_igemm<1, 3, 2>,
                         cudaFuncAttributeMaxDynamicSharedMemorySize, SME);
    cudaFuncSetAttribute(mma_igemm<0, 3, 2>,
                         cudaFuncAttributeMaxDynamicSharedMemorySize, SME);
    cudaFuncSetAttribute(mma_igemm<0, 3, 1>,
                         cudaFuncAttributeMaxDynamicSharedMemorySize, SME);
    cudaFuncSetAttribute(mma_igemm<2, 1, 4>,
                         cudaFuncAttributeMaxDynamicSharedMemorySize, SMD);
    cudaFuncSetAttribute(mma_igemm<2, 1, 1>,
                         cudaFuncAttributeMaxDynamicSharedMemorySize, SMD);
    cudaFuncSetAttribute(convt3_v2,
                         cudaFuncAttributeMaxDynamicSharedMemorySize, SMT3);

    // 3 pre-launches (conv3 lands on ncu slot 5)
    halo_zero<<<4096, 256>>>(h1hi, h1lo, h2hi, h2lo);
    xform_misc<<<(825856 + 255) / 256, 256>>>(ew1, w1hi, w1lo, pw, wtp,
                                              dw1, wd1, dw2, wd2, emb, e2);
    pack_fwd<<<(15204352 + 255) / 256, 256>>>(ew2, w2hi, w2lo, ew3, w3hi,
                                              w3lo, x, ximhi, ximlo);

    MP m;
    m.xh = (const __half*)0; m.xl = (const __half*)0;
    m.x = (const uint32_t*)0; m.x2 = (const uint32_t*)0;

    // conv1 (dense pair-words): xim -> h1 planes
    m.x = ximhi; m.x2 = ximlo;
    m.whi = (const uint32_t*)w1hi; m.wlo = (const uint32_t*)w1lo;
    m.bias = eb1; m.out = h1hi; m.out2 = h1lo;
    m.Cin = 3; m.Hin = 256; m.Win = 256; m.Mtot = 128;
    m.Hout = 128; m.Wout = 128; m.K = 48; m.sHWo = 14; m.sW = 7;
    mma_igemm<1, 3, 2><<<dim3(4096, 1), 256, SME>>>(m);

    // conv2 (halo planes): h1 -> h2 planes
    m.xh = h1hi; m.xl = h1lo; m.x = (const uint32_t*)0;
    m.whi = (const uint32_t*)w2hi; m.wlo = (const uint32_t*)w2lo;
    m.bias = eb2; m.out = h2hi; m.out2 = h2lo;
    m.Cin = 128; m.Hin = 128; m.Win = 128; m.Mtot = 256;
    m.Hout = 64; m.Wout = 64; m.K = 2048; m.sHWo = 12; m.sW = 6;
    mma_igemm<0, 3, 2><<<dim3(1024, 2), 256, SME>>>(m);

    // conv3 (halo planes): h2 -> h3 fp32 flat
    m.xh = h2hi; m.xl = h2lo;
    m.whi = (const uint32_t*)w3hi; m.wlo = (const uint32_t*)w3lo;
    m.bias = eb3; m.out = h3; m.out2 = h3;
    m.Cin = 256; m.Hin = 64; m.Win = 64; m.Mtot = 512;
    m.Hout = 32; m.Wout = 32; m.K = 4096; m.sHWo = 10; m.sW = 5;
    mma_igemm<0, 3, 1><<<dim3(256, 4), 256, SME>>>(m);

    // pre-VQ 1x1 (SIMT fp32): h3 -> ze
    GP g;
    g.x = h3; g.wt = wtp; g.bias = pb; g.out = ze;
    g.Cin = 512; g.Hin = 1; g.Win = 1024; g.M = 64;
    g.K = 512; g.sHWo = 10; g.sW = 0;
    igemm1x1<0><<<dim3(32768 / 64, 1), 256>>>(g);

    // VQ (zq as half2 words)
    vq_kernel<<<256, 128>>>(ze, emb, e2, zq, part);
    vq_loss_kernel<<<1, 256>>>(part, out + 6291456);

    // convT1 (fp16 1x): zq -> d1 (half2 words), 4 pars via grid z
    m.xh = (const __half*)0; m.xl = (const __half*)0;
    m.x = zq; m.x2 = zq;
    m.whi = (const uint32_t*)wd1; m.wlo = (const uint32_t*)wd1;
    m.bias = db1; m.out = d1b; m.out2 = d1b;
    m.Cin = 64; m.Hin = 32; m.Win = 32; m.Mtot = 256;
    m.Hout = 64; m.Wout = 64; m.K = 256; m.sHWo = 10; m.sW = 5;
    mma_igemm<2, 1, 4><<<dim3(256, 2, 4), 256, SMD>>>(m);

    // convT2 (fp16 1x): d1 -> d2 fp32, 4 pars via grid z
    m.x = d1b; m.x2 = d1b;
    m.whi = (const uint32_t*)wd2; m.wlo = (const uint32_t*)wd2;
    m.bias = db2; m.out = d2b; m.out2 = d2b;
    m.Cin = 256; m.Hin = 64; m.Win = 64; m.Mtot = 128;
    m.Hout = 128; m.Wout = 128; m.K = 1024; m.sHWo = 12; m.sW = 6;
    mma_igemm<2, 1, 1><<<dim3(1024, 1, 4), 256, SMD>>>(m);

    // convT3 v2 (smem-tiled) + sigmoid
    convt3_v2<<<dim3(1, 128, 32), 256, SMT3>>>(d2b, dw3, db3, out);
}